// round 14
// baseline (speedup 1.0000x reference)
#include <cuda_runtime.h>
#include <cuda.h>
#include <cuda_bf16.h>
#include <cstdint>

#define BB 256
#define TT 336
#define DD 128
#define HH 1024
#define K1 1152
#define K2 2048
#define FOURH 4096

#define NSTG 6
#define STB 24576                  // A 16KB + B 8KB
#define ZS_OFF (NSTG * STB + 1024)            // dedicated zs region (no aliasing)
#define SMEM_CG2 (ZS_OFF + 128 * 133 * 4)     // = 216576 B
#define NCTA 64
#define PF 5                       // prefetch depth across GEMM boundary
#define NGEMM (TT * 2)

// ---- arch-feature gate ----
#if defined(__CUDA_ARCH__) && \
    (defined(__CUDA_ARCH_FEAT_SM103_ALL) || defined(__CUDA_ARCH_FEAT_SM100_ALL) || \
     (defined(__CUDA_ARCH_SPECIFIC__) && (__CUDA_ARCH_SPECIFIC__ >= 1000)) || \
     (defined(__CUDA_ARCH_FAMILY_SPECIFIC__) && (__CUDA_ARCH_FAMILY_SPECIFIC__ >= 1000)))
#define HAS_TCGEN05 1
#else
#define HAS_TCGEN05 0
#endif

// ---------------- device-global scratch ----------------
// tc layout: Wp[(w>>5)*128 + g*32 + (w&31)][K]  (gate blocks of 32 cols)
__device__ __nv_bfloat16 g_W1[K1 * FOURH];
__device__ __nv_bfloat16 g_W2[K2 * FOURH];
__device__ __nv_bfloat16 g_X[TT * BB * DD];  // [t][b][d]
__device__ __nv_bfloat16 g_h1[2][BB * HH];
__device__ __nv_bfloat16 g_h2[2][BB * HH];
__device__ float g_c1[BB * HH];
__device__ float g_c2[BB * HH];
__device__ float g_partial[BB];
__device__ unsigned g_bar_ctr;

// ---------------- helpers ----------------
__device__ __forceinline__ uint32_t smem_u32(const void* p) {
    return (uint32_t)__cvta_generic_to_shared(p);
}
__device__ __forceinline__ float fast_tanh(float x) {
    float y;
    asm("tanh.approx.f32 %0, %1;" : "=f"(y) : "f"(x));
    return y;
}
__device__ __forceinline__ float fast_sigmoid(float x) {
    return 0.5f * fast_tanh(0.5f * x) + 0.5f;
}
__device__ __forceinline__ float sigmoidf_(float x) { return 1.f / (1.f + __expf(-x)); }

// ---------------- fused prelude (tc mode): W transposes + X convert + init ----
#define PRE_W1 (36 * 32 * 4)
#define PRE_W2 (64 * 32 * 4)
#define PRE_X  592
#define PRE_I  512
#define PRE_TOT (PRE_W1 + PRE_W2 + PRE_X + PRE_I)

__global__ void prelude_tc(const float* __restrict__ W1s, const float* __restrict__ W2s,
                           const float* __restrict__ f) {
    __shared__ float tile[32][33];
    const int bid = blockIdx.x;
    const int tid = threadIdx.x;
    if (bid < PRE_W1 + PRE_W2) {
        const float* src;
        __nv_bfloat16* dst;
        int K, kb, wb, g;
        if (bid < PRE_W1) {
            src = W1s; dst = g_W1; K = K1;
            kb = (bid % 36) * 32;
            int rest = bid / 36;
            wb = (rest & 31) * 32;
            g = rest >> 5;
        } else {
            int b2 = bid - PRE_W1;
            src = W2s; dst = g_W2; K = K2;
            kb = (b2 & 63) * 32;
            int rest = b2 >> 6;
            wb = (rest & 31) * 32;
            g = rest >> 5;
        }
        const int tx = tid & 31, ty0 = tid >> 5;
#pragma unroll
        for (int i = 0; i < 4; i++) {
            int ty = ty0 + i * 8;
            tile[ty][tx] = src[(size_t)(kb + ty) * FOURH + g * HH + wb + tx];
        }
        __syncthreads();
#pragma unroll
        for (int i = 0; i < 4; i++) {
            int ty = ty0 + i * 8;
            int w = wb + ty;
            int row = (w >> 5) * 128 + g * 32 + (w & 31);
            dst[(size_t)row * K + kb + tx] = __float2bfloat16(tile[tx][ty]);
        }
    } else if (bid < PRE_W1 + PRE_W2 + PRE_X) {
        int lb = bid - (PRE_W1 + PRE_W2);
        int n = BB * TT * DD;
        for (int i = lb * 256 + tid; i < n; i += PRE_X * 256) {
            int b = i / (TT * DD);
            int r2 = i % (TT * DD);
            int tt = r2 / DD, d = r2 % DD;
            g_X[(size_t)tt * BB * DD + b * DD + d] = __float2bfloat16(f[i]);
        }
    } else {
        int lb = bid - (PRE_W1 + PRE_W2 + PRE_X);
        if (lb == 0 && tid == 0) g_bar_ctr = 0;
        __nv_bfloat16 z = __float2bfloat16(0.f);
        int n = BB * HH;
        for (int i = lb * 256 + tid; i < n; i += PRE_I * 256) {
            g_c1[i] = 0.f;
            g_c2[i] = 0.f;
            g_h1[0][i] = z;
            g_h2[0][i] = z;
        }
    }
}

// ---------------- fallback-mode conversion / init kernels ----------------
__global__ void conv_w_kernel(const float* __restrict__ src, int which, int n) {
    for (int i = blockIdx.x * blockDim.x + threadIdx.x; i < n; i += gridDim.x * blockDim.x) {
        __nv_bfloat16 v = __float2bfloat16(src[i]);
        if (which == 0) g_W1[i] = v;
        else            g_W2[i] = v;
    }
}

__global__ void conv_x_kernel(const float* __restrict__ f) {
    int n = BB * TT * DD;
    for (int i = blockIdx.x * blockDim.x + threadIdx.x; i < n; i += gridDim.x * blockDim.x) {
        int b = i / (TT * DD);
        int r = i % (TT * DD);
        int t = r / DD;
        int d = r % DD;
        g_X[(size_t)t * BB * DD + b * DD + d] = __float2bfloat16(f[i]);
    }
}

__global__ void init_state_kernel() {
    int n = BB * HH;
    __nv_bfloat16 z = __float2bfloat16(0.f);
    if (blockIdx.x == 0 && threadIdx.x == 0) g_bar_ctr = 0;
    for (int i = blockIdx.x * blockDim.x + threadIdx.x; i < n; i += gridDim.x * blockDim.x) {
        g_c1[i] = 0.f;
        g_c2[i] = 0.f;
        g_h1[0][i] = z;
        g_h2[0][i] = z;
    }
}

// ============================================================================
// tcgen05 + TMA PTX helpers ('a'-variant targets only)
// ============================================================================
#if HAS_TCGEN05

__device__ __forceinline__ uint32_t elect_one_pred() {
    uint32_t pred;
    asm volatile(
        "{\n\t.reg .pred p;\n\t"
        "elect.sync _|p, 0xFFFFFFFF;\n\t"
        "selp.b32 %0, 1, 0, p;\n\t}"
        : "=r"(pred));
    return pred;
}

#define MBARRIER_INIT(mbar, count) \
    asm volatile("mbarrier.init.shared.b64 [%0], %1;" :: "r"((uint32_t)(mbar)), "r"((uint32_t)(count)) : "memory")

#define MBARRIER_EXPECT_TX(mbar, bytes) \
    asm volatile("mbarrier.arrive.expect_tx.shared.b64 _, [%0], %1;" \
                 :: "r"((uint32_t)(mbar)), "r"((uint32_t)(bytes)) : "memory")

#define MBARRIER_ARRIVE(mbar) \
    asm volatile("mbarrier.arrive.shared.b64 _, [%0];" :: "r"((uint32_t)(mbar)) : "memory")

#define MBARRIER_ARRIVE_CLUSTER(local_mbar, target_rank) \
    asm volatile( \
        "{\n\t.reg .b32 remAddr;\n\t" \
        "mapa.shared::cluster.u32 remAddr, %0, %1;\n\t" \
        "mbarrier.arrive.shared::cluster.b64 _, [remAddr];\n\t}" \
        :: "r"((uint32_t)(local_mbar)), "r"((uint32_t)(target_rank)) : "memory")

#define MBARRIER_WAIT_PARITY(mbar_addr, phase_parity) do {                          \
    uint32_t _mbar = (uint32_t)(mbar_addr);                                         \
    uint32_t _parity = (uint32_t)(phase_parity);                                    \
    uint32_t _done;                                                                 \
    asm volatile(                                                                   \
        "{\n\t.reg .pred p;\n\t"                                                    \
        "mbarrier.try_wait.parity.acquire.cta.shared::cta.b64 p, [%1], %2;\n\t"     \
        "selp.b32 %0, 1, 0, p;\n\t}"                                                \
        : "=r"(_done) : "r"(_mbar), "r"(_parity) : "memory");                       \
    if (!_done) {                                                                   \
        asm volatile(                                                               \
            "{\n\t.reg .pred P1;\n\t"                                               \
            "WAIT_LOOP_%=:\n\t"                                                     \
            "mbarrier.try_wait.parity.acquire.cta.shared::cta.b64 P1, [%0], %1, 0x989680;\n\t" \
            "@P1 bra.uni WAIT_DONE_%=;\n\t"                                         \
            "bra.uni WAIT_LOOP_%=;\n\t"                                             \
            "WAIT_DONE_%=:\n\t}"                                                    \
            :: "r"(_mbar), "r"(_parity) : "memory");                                \
    }                                                                               \
} while (0)

#define TMA_LOAD_3D(smem_addr, tensor_map, cx, cy, cz, mbar) \
    asm volatile( \
        "cp.async.bulk.tensor.3d.shared::cta.global.tile.mbarrier::complete_tx::bytes " \
        "[%0], [%1, {%2, %3, %4}], [%5];" \
        :: "r"((uint32_t)(smem_addr)), "l"(tensor_map), \
           "r"((int32_t)(cx)), "r"((int32_t)(cy)), "r"((int32_t)(cz)), \
           "r"((uint32_t)(mbar)) \
        : "memory")

#define TMA_LOAD_3D_MULTICAST(smem_addr, tensor_map, cx, cy, cz, mbar, cta_mask) \
    asm volatile( \
        "cp.async.bulk.tensor.3d.shared::cluster.global.tile.mbarrier::complete_tx::bytes.multicast::cluster " \
        "[%0], [%1, {%2, %3, %4}], [%5], %6;" \
        :: "r"((uint32_t)(smem_addr)), "l"(tensor_map), \
           "r"((int32_t)(cx)), "r"((int32_t)(cy)), "r"((int32_t)(cz)), \
           "r"((uint32_t)(mbar)), "h"((uint16_t)(cta_mask)) \
        : "memory")

#define CLUSTER_SYNC() do { \
    asm volatile("barrier.cluster.arrive.aligned;" ::: "memory"); \
    asm volatile("barrier.cluster.wait.aligned;" ::: "memory"); \
} while (0)

#define NAMED_BARRIER_SYNC(barrier_id, thread_count) \
    asm volatile("bar.sync %0, %1;" :: "r"(barrier_id), "r"(thread_count) : "memory")

#define TCGEN05_ALLOC_CG2(smem_result_addr, nCols) \
    asm volatile("tcgen05.alloc.cta_group::2.sync.aligned.shared::cta.b32 [%0], %1;" \
                 :: "r"((uint32_t)(smem_result_addr)), "r"((uint32_t)(nCols)) : "memory")
#define TCGEN05_DEALLOC_CG2(tmem_addr, nCols) \
    asm volatile("tcgen05.dealloc.cta_group::2.sync.aligned.b32 %0, %1;" \
                 :: "r"(tmem_addr), "r"((uint32_t)(nCols)))
#define TCGEN05_RELINQUISH_CG2() \
    asm volatile("tcgen05.relinquish_alloc_permit.cta_group::2.sync.aligned;")
#define TCGEN05_COMMIT_MC_CG2(mbar_addr, cta_mask) \
    asm volatile("tcgen05.commit.cta_group::2.mbarrier::arrive::one.shared::cluster.multicast::cluster.b64 [%0], %1;" \
                 :: "r"((uint32_t)(mbar_addr)), "h"((uint16_t)(cta_mask)) : "memory")
#define TCGEN05_WAIT_LD()  asm volatile("tcgen05.wait::ld.sync.aligned;" ::: "memory")
#define TCGEN05_FENCE_AFTER()  asm volatile("tcgen05.fence::after_thread_sync;" ::: "memory")
#define TCGEN05_FENCE_BEFORE() asm volatile("tcgen05.fence::before_thread_sync;" ::: "memory")

#define TCGEN05_LD_X32(r, tmem_addr) \
    asm volatile( \
        "tcgen05.ld.sync.aligned.32x32b.x32.b32 " \
        "{%0, %1, %2, %3, %4, %5, %6, %7, " \
        " %8, %9, %10, %11, %12, %13, %14, %15, " \
        " %16, %17, %18, %19, %20, %21, %22, %23, " \
        " %24, %25, %26, %27, %28, %29, %30, %31}, [%32];" \
        : "=r"((r)[0]),  "=r"((r)[1]),  "=r"((r)[2]),  "=r"((r)[3]), \
          "=r"((r)[4]),  "=r"((r)[5]),  "=r"((r)[6]),  "=r"((r)[7]), \
          "=r"((r)[8]),  "=r"((r)[9]),  "=r"((r)[10]), "=r"((r)[11]), \
          "=r"((r)[12]), "=r"((r)[13]), "=r"((r)[14]), "=r"((r)[15]), \
          "=r"((r)[16]), "=r"((r)[17]), "=r"((r)[18]), "=r"((r)[19]), \
          "=r"((r)[20]), "=r"((r)[21]), "=r"((r)[22]), "=r"((r)[23]), \
          "=r"((r)[24]), "=r"((r)[25]), "=r"((r)[26]), "=r"((r)[27]), \
          "=r"((r)[28]), "=r"((r)[29]), "=r"((r)[30]), "=r"((r)[31]) \
        : "r"(tmem_addr))

__device__ __forceinline__ uint64_t sdesc_sw128(uint32_t addr) {
    return (2ULL << 61) | (1ULL << 46) | (64ULL << 32) | (1ULL << 16) |
           (uint64_t)((addr >> 4) & 0x3FFF);
}

// idesc kind::f16 cg2: dtype=F32, atype=btype=BF16, N=128, M=256
#define IDESC_CG2 ((1u << 4) | (1u << 7) | (1u << 10) | (16u << 17) | (16u << 24))

__device__ __forceinline__ void mma_f16_ss_cg2(uint32_t d, uint64_t ad, uint64_t bd,
                                               uint32_t idesc, unsigned en) {
    asm volatile(
        "{\n\t.reg .pred p;\n\t"
        "setp.ne.u32 p, %6, 0;\n\t"
        "tcgen05.mma.cta_group::2.kind::f16 [%0], %1, %2, %3, "
        "{%4, %4, %4, %4, %4, %4, %4, %4}, p;\n\t}"
        :: "r"(d), "l"(ad), "l"(bd), "r"(idesc), "r"(0u), "r"(0u), "r"(en) : "memory");
}

#endif // HAS_TCGEN05

// ============================================================================
// PERSISTENT cg2 tcgen05 kernel with GEMM-level pipelining:
//   TMEM D double-buffered (256 cols); warp 0 = MMA/relay, warp 1 = producer,
//   warps 4-7 = epilogue crew (named barrier 1). No __syncthreads in mainloop.
//   epi_done[2] (count 2: leader crew + odd crew relay) gates D-buffer reuse.
//   Grid-barrier arrivals come from the crew; producer alone spins on it.
// ============================================================================
__global__ __launch_bounds__(256, 1)
void lstm_persist_cg2(const __grid_constant__ CUtensorMap tmx,
                      const __grid_constant__ CUtensorMap tmh1,
                      const __grid_constant__ CUtensorMap tmh2,
                      const __grid_constant__ CUtensorMap tmw1,
                      const __grid_constant__ CUtensorMap tmw2,
                      const float* __restrict__ b1, const float* __restrict__ b2) {
#if HAS_TCGEN05
    extern __shared__ __align__(1024) unsigned char sm[];
    const uint32_t smem_base = smem_u32(sm);
    const int tid = threadIdx.x;
    const int wid = tid >> 5;
    const int lane = tid & 31;

    const int r = (int)(blockIdx.x & 3);
    const int ntg = (int)((blockIdx.x >> 2) * 2 + (r >> 1));
    const int m0 = (r & 1) * 128;
    const int ar = r >> 1;                 // A slice index within same-m pair
    const int leader = ((r & 1) == 0);
    const uint16_t amask = (uint16_t)((1u << r) | (1u << (r ^ 2)));
    const uint16_t pairmask = (uint16_t)(0x3u << (r & ~1));

    const uint32_t ctrl = smem_base + NSTG * STB;          // tmem ptr (16B)
    const uint32_t mb_full = ctrl + 16;
    const uint32_t mb_empty = mb_full + 8 * NSTG;
    const uint32_t mb_done = mb_empty + 8 * NSTG;
    const uint32_t mb_epi = mb_done + 8;                   // epi_done[2]
    float* zs = (float*)(sm + ZS_OFF);                     // [128][133], dedicated

    if (wid == 0) TCGEN05_ALLOC_CG2(ctrl, 256);
    if (tid == 0) {
#pragma unroll
        for (int s = 0; s < NSTG; s++) {
            MBARRIER_INIT(mb_full + 8 * s, leader ? 2 : 1);
            MBARRIER_INIT(mb_empty + 8 * s, 2);
        }
        MBARRIER_INIT(mb_done, 1);
        MBARRIER_INIT(mb_epi, 2);
        MBARRIER_INIT(mb_epi + 8, 2);
    }
    __syncthreads();
    CLUSTER_SYNC();
    uint32_t tmem_base;
    asm volatile("ld.shared.b32 %0, [%1];" : "=r"(tmem_base) : "r"(ctrl));

    if (wid == 1) {
        // =================== PRODUCER (R13 logic, flat over GEMMs) ===========
        auto issue_A = [&](int layer_, int t_, int c, uint32_t sbase, uint32_t fb) {
            const int k0 = c * 64;
            const int pin_ = t_ & 1, pout_ = pin_ ^ 1;
            const CUtensorMap* tA;
            int cx, cz;
            if (layer_ == 0) {
                if (k0 < DD) { tA = &tmx;  cx = k0;      cz = t_; }
                else         { tA = &tmh1; cx = k0 - DD; cz = pin_; }
            } else {
                if (k0 < HH) { tA = &tmh1; cx = k0;      cz = pout_; }
                else         { tA = &tmh2; cx = k0 - HH; cz = pin_; }
            }
            TMA_LOAD_3D_MULTICAST(sbase + ar * 8192, tA, cx, m0 + ar * 64, cz, fb, amask);
        };
        auto issue_B = [&](int layer_, int c, uint32_t sbase, uint32_t fb) {
            const CUtensorMap* tB = (layer_ == 0) ? &tmw1 : &tmw2;
            TMA_LOAD_3D(sbase + 16384, tB, c * 64, ntg * 128 + (r & 1) * 64, 0, fb);
        };

        unsigned gj = 0;
        int pf = 0, pendA = 0;
        for (int gix = 0; gix < NGEMM; ++gix) {
            const int layer = gix & 1;
            const int t = gix >> 1;
            const int nc = (layer == 0) ? (K1 / 64) : (K2 / 64);
            // wait for all epilogues < gix to be globally visible (h freshness)
            if (gix > 0) {
                if (lane == 0) {
                    const unsigned tgt = (unsigned)gix * (unsigned)NCTA;
                    while (*(volatile unsigned*)&g_bar_ctr < tgt) { }
                }
                __syncwarp();
                asm volatile("fence.proxy.async;" ::: "memory");
            }
            if (pendA) {
                if (elect_one_pred()) {
                    for (int c = 0; c < pf; ++c) {
                        const int s = (int)((gj + (unsigned)c) % NSTG);
                        issue_A(layer, t, c, smem_base + s * STB, mb_full + 8 * s);
                    }
                }
                pendA = 0;
            }
            for (int c = pf; c < nc; ++c) {
                const unsigned G = gj + (unsigned)c;
                const int s = (int)(G % NSTG);
                const unsigned n = G / NSTG;
                if (n > 0) MBARRIER_WAIT_PARITY(mb_empty + 8 * s, (int)((n - 1) & 1));
                if (elect_one_pred()) {
                    const uint32_t sbase = smem_base + s * STB;
                    const uint32_t fb = mb_full + 8 * s;
                    MBARRIER_EXPECT_TX(fb, (uint32_t)STB);
                    issue_A(layer, t, c, sbase, fb);
                    issue_B(layer, c, sbase, fb);
                }
            }
            // prefetch next GEMM
            if (gix + 1 < NGEMM) {
                const int nlayer = layer ^ 1;
                const int nt_ = (layer == 0) ? t : t + 1;
                const int next_nc = (nlayer == 0) ? (K1 / 64) : (K2 / 64);
                const int npf = (PF < next_nc) ? PF : next_nc;
                for (int c2 = 0; c2 < npf; ++c2) {
                    const unsigned G = gj + (unsigned)nc + (unsigned)c2;
                    const int s = (int)(G % NSTG);
                    const unsigned n = G / NSTG;
                    if (n > 0) MBARRIER_WAIT_PARITY(mb_empty + 8 * s, (int)((n - 1) & 1));
                    if (elect_one_pred()) {
                        const uint32_t sbase = smem_base + s * STB;
                        const uint32_t fb = mb_full + 8 * s;
                        MBARRIER_EXPECT_TX(fb, (uint32_t)STB);
                        issue_B(nlayer, c2, sbase, fb);
                        if (nlayer == 0) issue_A(nlayer, nt_, c2, sbase, fb);
                    }
                }
                pf = npf;
                pendA = (nlayer == 1);
            }
            gj += (unsigned)nc;
        }
    } else if (wid == 0) {
        if (leader) {
            // =================== CONSUMER: cg2 MMA issuer =====================
            unsigned gj = 0;
            for (int gix = 0; gix < NGEMM; ++gix) {
                const int nc = ((gix & 1) == 0) ? (K1 / 64) : (K2 / 64);
                const int b = gix & 1;
                // gate on D buffer free (epilogue of gix-2 done)
                if (gix >= 2)
                    MBARRIER_WAIT_PARITY(mb_epi + 8 * b, (int)(((gix >> 1) - 1) & 1));
                const uint32_t dD = tmem_base + (uint32_t)b * 128;
                for (int c = 0; c < nc; ++c) {
                    const unsigned G = gj + (unsigned)c;
                    const int s = (int)(G % NSTG);
                    const unsigned n = G / NSTG;
                    MBARRIER_WAIT_PARITY(mb_full + 8 * s, (int)(n & 1));
                    if (elect_one_pred()) {
                        const uint64_t ad = sdesc_sw128(smem_base + s * STB);
                        const uint64_t bd = sdesc_sw128(smem_base + s * STB + 16384);
#pragma unroll
                        for (int kk = 0; kk < 4; kk++)
                            mma_f16_ss_cg2(dD, ad + kk * 2, bd + kk * 2,
                                           IDESC_CG2, (unsigned)((c | kk) != 0));
                        TCGEN05_COMMIT_MC_CG2(mb_empty + 8 * s, 0xFu);
                    }
                }
                if (elect_one_pred()) TCGEN05_COMMIT_MC_CG2(mb_done, pairmask);
                gj += (unsigned)nc;
            }
        } else {
            // =================== odd rank: relay full -> leader ==============
            unsigned gj = 0;
            for (int gix = 0; gix < NGEMM; ++gix) {
                const int nc = ((gix & 1) == 0) ? (K1 / 64) : (K2 / 64);
                for (int c = 0; c < nc; ++c) {
                    const unsigned G = gj + (unsigned)c;
                    const int s = (int)(G % NSTG);
                    const unsigned n = G / NSTG;
                    MBARRIER_WAIT_PARITY(mb_full + 8 * s, (int)(n & 1));
                    if (elect_one_pred())
                        MBARRIER_ARRIVE_CLUSTER(mb_full + 8 * s, r - 1);
                }
                gj += (unsigned)nc;
            }
        }
    } else if (wid >= 4) {
        // =================== EPILOGUE CREW (warps 4-7) ========================
        constexpr int ZSTRIDE = 133;
        const int row = (wid & 3) * 32 + lane;     // this warp's TMEM lanes
        const int tid2 = (wid - 4) * 32 + lane;    // 0..127
        for (int gix = 0; gix < NGEMM; ++gix) {
            const int layer = gix & 1;
            const int t = gix >> 1;
            const int pout = (t & 1) ^ 1;
            float* cst = (layer == 0) ? g_c1 : g_c2;
            __nv_bfloat16* hout = (layer == 0) ? g_h1[pout] : g_h2[pout];
            const float* bias = (layer == 0) ? b1 : b2;
            const uint32_t boff = (uint32_t)(gix & 1) * 128;

            MBARRIER_WAIT_PARITY(mb_done, gix & 1);
            TCGEN05_FENCE_AFTER();

            uint32_t regs[64];
            TCGEN05_LD_X32(regs, tmem_base + boff);
            TCGEN05_LD_X32(regs + 32, tmem_base + boff + 32);
            TCGEN05_WAIT_LD();
#pragma unroll
            for (int c2 = 0; c2 < 64; c2++)
                zs[row * ZSTRIDE + c2] = __uint_as_float(regs[c2]);
            TCGEN05_LD_X32(regs, tmem_base + boff + 64);
            TCGEN05_LD_X32(regs + 32, tmem_base + boff + 96);
            TCGEN05_WAIT_LD();
#pragma unroll
            for (int c2 = 0; c2 < 64; c2++)
                zs[row * ZSTRIDE + 64 + c2] = __uint_as_float(regs[c2]);
            TCGEN05_FENCE_BEFORE();
            NAMED_BARRIER_SYNC(1, 128);
            // D buffer free -> release consumer (both CTAs must arrive on leader)
            if (wid == 4 && lane == 0) {
                if (leader) MBARRIER_ARRIVE(mb_epi + 8 * (gix & 1));
                else        MBARRIER_ARRIVE_CLUSTER(mb_epi + 8 * (gix & 1), r - 1);
            }

            const int hb = ntg * 32;
#pragma unroll 4
            for (int e = tid2; e < 128 * 32; e += 128) {
                const int rr = e >> 5;
                const int hc = e & 31;
                float zi = zs[rr * ZSTRIDE + hc]      + bias[hb + hc];
                float zj = zs[rr * ZSTRIDE + 32 + hc] + bias[HH + hb + hc];
                float zf = zs[rr * ZSTRIDE + 64 + hc] + bias[2 * HH + hb + hc];
                float zo = zs[rr * ZSTRIDE + 96 + hc] + bias[3 * HH + hb + hc];
                const int gi = (m0 + rr) * HH + hb + hc;
                float cc = cst[gi];
                float ncell = cc * fast_sigmoid(zf + 1.f) +
                              fast_sigmoid(zi) * fast_tanh(zj);
                hout[gi] = __float2bfloat16(fast_tanh(ncell) * fast_sigmoid(zo));
                cst[gi] = ncell;
            }
            NAMED_BARRIER_SYNC(1, 128);
            if (wid == 4 && lane == 0) {
                __threadfence();
                atomicAdd(&g_bar_ctr, 1u);
            }
        }
    }
    // warps 2,3 fall through (idle)

    CLUSTER_SYNC();
    if (wid == 0) {
        TCGEN05_RELINQUISH_CG2();
        TCGEN05_DEALLOC_CG2(tmem_base, 256);
    }
#endif // HAS_TCGEN05
}

// ============================================================================
// Fallback: mma.sync (HMMA) fused step kernel (round-1 proven path).
// ============================================================================
#define AS_STRIDE 40
#define BS_STRIDE 136
#define ZS_STRIDE 132

__global__ __launch_bounds__(256, 1)
void lstm_step_fb(int layer, int t, int pin, const float* __restrict__ bias) {
    __shared__ __align__(16) unsigned char smem_raw[64 * ZS_STRIDE * 4];
    __nv_bfloat16* As = (__nv_bfloat16*)smem_raw;
    __nv_bfloat16* Bs = (__nv_bfloat16*)(smem_raw + 10240);
    float* zs = (float*)smem_raw;

    int K, boundk, lda0;
    const __nv_bfloat16 *A0, *A1, *Wm;
    float* cst;
    __nv_bfloat16* hout;
    const int pout = pin ^ 1;

    if (layer == 0) {
        K = K1; boundk = DD; lda0 = DD;
        A0 = g_X + (size_t)t * BB * DD;
        A1 = g_h1[pin];
        Wm = g_W1; cst = g_c1; hout = g_h1[pout];
    } else {
        K = K2; boundk = HH; lda0 = HH;
        A0 = g_h1[pout];
        A1 = g_h2[pin];
        Wm = g_W2; cst = g_c2; hout = g_h2[pout];
    }

    const int n0 = blockIdx.x * 32;
    const int m0 = blockIdx.y * 64;
    const int tid = threadIdx.x;
    const int lane = tid & 31;
    const int wid = tid >> 5;
    const int wm = wid & 3;
    const int wn = wid >> 2;
    const int rowA = tid >> 2;
    const int quadA = tid & 3;

    float acc[8][4];
#pragma unroll
    for (int j = 0; j < 8; j++)
#pragma unroll
        for (int q = 0; q < 4; q++) acc[j][q] = 0.f;

    auto load_stage = [&](int kt, int s) {
        const int k0 = kt * 32;
        const __nv_bfloat16* gpA;
        if (k0 < boundk) gpA = A0 + (size_t)(m0 + rowA) * lda0 + k0 + quadA * 8;
        else             gpA = A1 + (size_t)(m0 + rowA) * HH + (k0 - boundk) + quadA * 8;
        uint32_t dstA = smem_u32(As + s * 64 * AS_STRIDE + rowA * AS_STRIDE + quadA * 8);
        asm volatile("cp.async.cg.shared.global [%0], [%1], 16;\n" :: "r"(dstA), "l"(gpA));
#pragma unroll
        for (int i = 0; i < 2; i++) {
            int c = tid + i * 256;
            int kk = c >> 4;
            int ncv = (c & 15) * 8;
            int g = ncv >> 5;
            int col = g * HH + n0 + (ncv & 31);
            const __nv_bfloat16* gpB = Wm + (size_t)(k0 + kk) * FOURH + col;
            uint32_t dstB = smem_u32(Bs + s * 32 * BS_STRIDE + kk * BS_STRIDE + ncv);
            asm volatile("cp.async.cg.shared.global [%0], [%1], 16;\n" :: "r"(dstB), "l"(gpB));
        }
    };

    load_stage(0, 0);
    asm volatile("cp.async.commit_group;\n" ::: "memory");

    const int nK = K >> 5;
    for (int kt = 0; kt < nK; ++kt) {
        const int s = kt & 1;
        if (kt + 1 < nK) load_stage(kt + 1, s ^ 1);
        asm volatile("cp.async.commit_group;\n" ::: "memory");
        asm volatile("cp.async.wait_group 1;\n" ::: "memory");
        __syncthreads();

#pragma unroll
        for (int ks = 0; ks < 2; ++ks) {
            uint32_t a0, a1, a2, a3;
            {
                int row = wm * 16 + (lane & 15);
                int colb = ks * 16 + (lane >> 4) * 8;
                uint32_t addr = smem_u32(As + s * 64 * AS_STRIDE + row * AS_STRIDE + colb);
                asm volatile("ldmatrix.sync.aligned.m8n8.x4.shared.b16 {%0,%1,%2,%3}, [%4];\n"
                             : "=r"(a0), "=r"(a1), "=r"(a2), "=r"(a3) : "r"(addr));
            }
#pragma unroll
            for (int j2 = 0; j2 < 4; j2++) {
                uint32_t b0, b1, b2, b3;
                int krow = ks * 16 + (lane & 7) + ((lane >> 3) & 1) * 8;
                int ncol = wn * 64 + j2 * 16 + (lane >> 4) * 8;
                uint32_t addr = smem_u32(Bs + s * 32 * BS_STRIDE + krow * BS_STRIDE + ncol);
                asm volatile("ldmatrix.sync.aligned.m8n8.x4.trans.shared.b16 {%0,%1,%2,%3}, [%4];\n"
                             : "=r"(b0), "=r"(b1), "=r"(b2), "=r"(b3) : "r"(addr));
                asm volatile("mma.sync.aligned.m16n8k16.row.col.f32.bf16.bf16.f32 "
                             "{%0,%1,%2,%3}, {%4,%5,%6,%7}, {%8,%9}, {%0,%1,%2,%3};\n"
                             : "+f"(acc[2 * j2][0]), "+f"(acc[2 * j2][1]),
                               "+f"(acc[2 * j2][2]), "+f"(acc[2 * j2][3])
                             : "r"(a0), "r"(a1), "r"(a2), "r"(a3), "r"(b0), "r"(b1));
                asm volatile("mma.sync.aligned.m16n8k16.row.col.f32.bf16.bf16.f32 "
                             "{%0,%1,%2,%3}, {%4,%5,%6,%7}, {%8,%9}, {%0,%1,%2,%3};\n"
                             : "+f"(acc[2 * j2 + 1][0]), "+f"(acc[2 * j2 + 1][1]),
                               "+f"(acc[2 * j2 + 1][2]), "+f"(acc[2 * j2 + 1][3])
                             : "r"(a0), "r"(a1), "r"(a2), "r"(a3), "r"(b2), "r"(b3));
            }
        }
        __syncthreads();
    }

#pragma unroll
    for (int j = 0; j < 8; j++) {
        int col = wn * 64 + j * 8 + (lane & 3) * 2;
        int rr = wm * 16 + (lane >> 2);
        zs[rr * ZS_STRIDE + col]           = acc[j][0];
        zs[rr * ZS_STRIDE + col + 1]       = acc[j][1];
        zs[(rr + 8) * ZS_STRIDE + col]     = acc[j][2];
        zs[(rr + 8) * ZS_STRIDE + col + 1] = acc[j][3];
    }
    __syncthreads();

#pragma unroll
    for (int e = tid; e < 64 * 32; e += 256) {
        int rr = e >> 5;
        int hc = e & 31;
        float zi = zs[rr * ZS_STRIDE + hc]        + bias[0 * HH + n0 + hc];
        float zj = zs[rr * ZS_STRIDE + 32 + hc]   + bias[1 * HH + n0 + hc];
        float zf = zs[rr * ZS_STRIDE + 64 + hc]   + bias[2 * HH + n0 + hc];
        float zo = zs[rr * ZS_STRIDE + 96 + hc]   + bias[3 * HH + n0 + hc];
        int gi = (m0 + rr) * HH + n0 + hc;
        float c = cst[gi];
        float ncell = c * sigmoidf_(zf + 1.f) + sigmoidf_(zi) * tanhf(zj);
        float nh = tanhf(ncell) * sigmoidf_(zo);
        cst[gi] = ncell;
        hout[gi] = __float2bfloat16(nh);
    }
}

// ---------------- dense head + loss ----------------
__global__ void head_kernel(const float* __restrict__ Wd, const float* __restrict__ bd,
                            const float* __restrict__ labels) {
    const int b = blockIdx.x;
    const int lane = threadIdx.x & 31;
    const int w = threadIdx.x >> 5;
    const __nv_bfloat16* h = g_h2[0];  // T=336 even -> final h2 in slot 0
    __shared__ float warpsum[8];
    float total = 0.f;
    for (int l = w; l < 24; l += 8) {
        float s = 0.f;
        for (int k = lane; k < HH; k += 32)
            s += __bfloat162float(h[b * HH + k]) * Wd[k * 24 + l];
#pragma unroll
        for (int off = 16; off; off >>= 1) s += __shfl_xor_sync(0xffffffffu, s, off);
        if (lane == 0) {
            float pred = s + bd[l];
            float e = pred - labels[b * 24 + l];
            total += e * e;
        }
    }
    if (lane == 0) warpsum[w] = total;
    __syncthreads();
    if (threadIdx.x == 0) {
        float acc = 0.f;
#pragma unroll
        for (int i = 0; i < 8; i++) acc += warpsum[i];
        g_partial[b] = acc;
    }
}

__global__ void finish_kernel(float* __restrict__ out) {
    __shared__ float sh[256];
    sh[threadIdx.x] = g_partial[threadIdx.x];
    __syncthreads();
    for (int s = 128; s; s >>= 1) {
        if (threadIdx.x < s) sh[threadIdx.x] += sh[threadIdx.x + s];
        __syncthreads();
    }
    if (threadIdx.x == 0) out[0] = sh[0] / (float)(BB * 24);
}

// ---------------- host: tensormap encoding ----------------
typedef CUresult (*encode_fn_t)(
    CUtensorMap*, CUtensorMapDataType, cuuint32_t, void*,
    const cuuint64_t*, const cuuint64_t*, const cuuint32_t*, const cuuint32_t*,
    CUtensorMapInterleave, CUtensorMapSwizzle, CUtensorMapL2promotion,
    CUtensorMapFloatOOBfill);

static bool encode_map(encode_fn_t enc, CUtensorMap* tm, void* base,
                       uint64_t d0, uint64_t d1, uint64_t d2,
                       uint64_t s1_bytes, uint64_t s2_bytes) {
    cuuint64_t dims[3] = {d0, d1, d2};
    cuuint64_t strides[2] = {s1_bytes, s2_bytes};
    cuuint32_t box[3] = {64, 64, 1};
    cuuint32_t es[3] = {1, 1, 1};
    CUresult res = enc(tm, CU_TENSOR_MAP_DATA_TYPE_BFLOAT16, 3, base,
                       dims, strides, box, es,
                       CU_TENSOR_MAP_INTERLEAVE_NONE, CU_TENSOR_MAP_SWIZZLE_128B,
                       CU_TENSOR_MAP_L2_PROMOTION_L2_128B,
                       CU_TENSOR_MAP_FLOAT_OOB_FILL_NONE);
    return res == CUDA_SUCCESS;
}

// ---------------- launch ----------------
extern "C" void kernel_launch(void* const* d_in, const int* in_sizes, int n_in,
                              void* d_out, int out_size) {
    const float* features = (const float*)d_in[0];
    const float* labels   = (const float*)d_in[1];
    const float* W1       = (const float*)d_in[2];
    const float* b1       = (const float*)d_in[3];
    const float* W2       = (const float*)d_in[4];
    const float* b2       = (const float*)d_in[5];
    const float* Wd       = (const float*)d_in[6];
    const float* bd       = (const float*)d_in[7];
    float* out = (float*)d_out;

    static CUtensorMap tmx, tmh1, tmh2, tmw1, tmw2;
    static int mode = -1;   // 0 = mma.sync fallback, 1 = cg2 persistent
    if (mode < 0) {
        mode = 0;
        cudaFuncAttributes attr{};
        cudaFuncGetAttributes(&attr, lstm_persist_cg2);
        if (attr.numRegs > 40) {
            void* fp = nullptr;
            cudaDriverEntryPointQueryResult qr = cudaDriverEntryPointSuccess;
            cudaGetDriverEntryPointByVersion("cuTensorMapEncodeTiled", &fp, 12000,
                                             cudaEnableDefault, &qr);
            void *px = nullptr, *ph1 = nullptr, *ph2 = nullptr, *pw1 = nullptr, *pw2 = nullptr;
            cudaGetSymbolAddress(&px, g_X);
            cudaGetSymbolAddress(&ph1, g_h1);
            cudaGetSymbolAddress(&ph2, g_h2);
            cudaGetSymbolAddress(&pw1, g_W1);
            cudaGetSymbolAddress(&pw2, g_W2);
            if (fp && px && ph1 && ph2 && pw1 && pw2) {
                encode_fn_t enc = (encode_fn_t)fp;
                bool ok = true;
                ok &= encode_map(enc, &tmx,  px,  DD, BB, TT, (uint64_t)DD * 2, (uint64_t)BB * DD * 2);
                ok &= encode_map(enc, &tmh1, ph1, HH, BB, 2,  (uint64_t)HH * 2, (uint64_t)BB * HH * 2);
                ok &= encode_map(enc, &tmh2, ph2, HH, BB, 2,  (uint64_t)HH * 2, (uint64_t)BB * HH * 2);
                ok &= encode_map(enc, &tmw1, pw1, K1, FOURH, 1, (uint64_t)K1 * 2, (uint64_t)K1 * FOURH * 2);
                ok &= encode_map(enc, &tmw2, pw2, K2, FOURH, 1, (uint64_t)K2 * 2, (uint64_t)K2 * FOURH * 2);
                if (ok && cudaFuncSetAttribute(lstm_persist_cg2,
                        cudaFuncAttributeMaxDynamicSharedMemorySize, SMEM_CG2) == cudaSuccess) {
                    mode = 1;
                }
            }
        }
    }

    if (mode == 1) {
        prelude_tc<<<PRE_TOT, 256>>>(W1, W2, features);

        cudaLaunchConfig_t cfg = {};
        cfg.gridDim = dim3(NCTA, 1, 1);
        cfg.blockDim = dim3(256, 1, 1);
        cfg.dynamicSmemBytes = SMEM_CG2;
        cudaLaunchAttribute at[1];
        at[0].id = cudaLaunchAttributeClusterDimension;
        at[0].val.clusterDim = {4, 1, 1};
        cfg.attrs = at;
        cfg.numAttrs = 1;
        cudaLaunchKernelEx(&cfg, lstm_persist_cg2, tmx, tmh1, tmh2, tmw1, tmw2, b1, b2);
    } else {
        conv_w_kernel<<<592, 256>>>(W1, 0, K1 * FOURH);
        conv_w_kernel<<<592, 256>>>(W2, 1, K2 * FOURH);
        conv_x_kernel<<<592, 256>>>(features);
        init_state_kernel<<<512, 256>>>();
        dim3 grid(32, 4);
        for (int t = 0; t < TT; t++) {
            int p = t & 1;
            lstm_step_fb<<<grid, 256>>>(0, t, p, b1);
            lstm_step_fb<<<grid, 256>>>(1, t, p, b2);
        }
    }

    head_kernel<<<BB, 256>>>(Wd, bd, labels);
    finish_kernel<<<1, 256>>>(out);
}

// round 15
// speedup vs baseline: 1.7443x; 1.7443x over previous
#include <cuda_runtime.h>
#include <cuda.h>
#include <cuda_bf16.h>
#include <cstdint>

#define BB 256
#define TT 336
#define DD 128
#define HH 1024
#define K1 1152
#define K2 2048
#define FOURH 4096

#define NSTG 6
#define STB 24576                  // A 16KB + B 8KB
#define ZS_OFF (NSTG * STB + 1024)            // dedicated zs region (no aliasing)
#define SMEM_CG2 (ZS_OFF + 128 * 133 * 4)     // = 216576 B
#define NCTA 64
#define PF 4                       // prefetch depth across GEMM boundary

// ---- arch-feature gate ----
#if defined(__CUDA_ARCH__) && \
    (defined(__CUDA_ARCH_FEAT_SM103_ALL) || defined(__CUDA_ARCH_FEAT_SM100_ALL) || \
     (defined(__CUDA_ARCH_SPECIFIC__) && (__CUDA_ARCH_SPECIFIC__ >= 1000)) || \
     (defined(__CUDA_ARCH_FAMILY_SPECIFIC__) && (__CUDA_ARCH_FAMILY_SPECIFIC__ >= 1000)))
#define HAS_TCGEN05 1
#else
#define HAS_TCGEN05 0
#endif

// ---------------- device-global scratch ----------------
// tc layout: Wp[(w>>5)*128 + g*32 + (w&31)][K]  (gate blocks of 32 cols)
__device__ __nv_bfloat16 g_W1[K1 * FOURH];
__device__ __nv_bfloat16 g_W2[K2 * FOURH];
__device__ __nv_bfloat16 g_X[TT * BB * DD];  // [t][b][d]
__device__ __nv_bfloat16 g_h1[2][BB * HH];
__device__ __nv_bfloat16 g_h2[2][BB * HH];
__device__ float g_c1[BB * HH];              // fallback path only
__device__ float g_c2[BB * HH];
__device__ float g_partial[BB];
__device__ unsigned g_bar_ctr;

// ---------------- helpers ----------------
__device__ __forceinline__ uint32_t smem_u32(const void* p) {
    return (uint32_t)__cvta_generic_to_shared(p);
}
__device__ __forceinline__ float fast_tanh(float x) {
    float y;
    asm("tanh.approx.f32 %0, %1;" : "=f"(y) : "f"(x));
    return y;
}
__device__ __forceinline__ float fast_sigmoid(float x) {
    return 0.5f * fast_tanh(0.5f * x) + 0.5f;
}
__device__ __forceinline__ float sigmoidf_(float x) { return 1.f / (1.f + __expf(-x)); }

// ---------------- conversion / init kernels ----------------
// tc path: W[k][4096] fp32 -> Wp[(w>>5)*128 + g*32 + (w&31)][K] bf16
__global__ void conv_w_t(const float* __restrict__ src, int which, int K) {
    __shared__ float tile[32][33];
    const int kb = blockIdx.x * 32, wb = blockIdx.y * 32, g = blockIdx.z;
    const int tx = threadIdx.x, ty0 = threadIdx.y;
#pragma unroll
    for (int i = 0; i < 4; i++) {
        int ty = ty0 + i * 8;
        tile[ty][tx] = src[(size_t)(kb + ty) * FOURH + g * HH + wb + tx];
    }
    __syncthreads();
    __nv_bfloat16* dst = (which == 0) ? g_W1 : g_W2;
#pragma unroll
    for (int i = 0; i < 4; i++) {
        int ty = ty0 + i * 8;
        int w = wb + ty;
        int row = (w >> 5) * 128 + g * 32 + (w & 31);
        dst[(size_t)row * K + kb + tx] = __float2bfloat16(tile[tx][ty]);
    }
}

__global__ void conv_w_kernel(const float* __restrict__ src, int which, int n) {
    for (int i = blockIdx.x * blockDim.x + threadIdx.x; i < n; i += gridDim.x * blockDim.x) {
        __nv_bfloat16 v = __float2bfloat16(src[i]);
        if (which == 0) g_W1[i] = v;
        else            g_W2[i] = v;
    }
}

__global__ void conv_x_kernel(const float* __restrict__ f) {
    int n = BB * TT * DD;
    for (int i = blockIdx.x * blockDim.x + threadIdx.x; i < n; i += gridDim.x * blockDim.x) {
        int b = i / (TT * DD);
        int r = i % (TT * DD);
        int t = r / DD;
        int d = r % DD;
        g_X[(size_t)t * BB * DD + b * DD + d] = __float2bfloat16(f[i]);
    }
}

__global__ void init_state_kernel() {
    int n = BB * HH;
    __nv_bfloat16 z = __float2bfloat16(0.f);
    if (blockIdx.x == 0 && threadIdx.x == 0) g_bar_ctr = 0;
    for (int i = blockIdx.x * blockDim.x + threadIdx.x; i < n; i += gridDim.x * blockDim.x) {
        g_c1[i] = 0.f;
        g_c2[i] = 0.f;
        g_h1[0][i] = z;
        g_h2[0][i] = z;
    }
}

// ============================================================================
// tcgen05 + TMA PTX helpers ('a'-variant targets only)
// ============================================================================
#if HAS_TCGEN05

__device__ __forceinline__ uint32_t elect_one_pred() {
    uint32_t pred;
    asm volatile(
        "{\n\t.reg .pred p;\n\t"
        "elect.sync _|p, 0xFFFFFFFF;\n\t"
        "selp.b32 %0, 1, 0, p;\n\t}"
        : "=r"(pred));
    return pred;
}

#define MBARRIER_INIT(mbar, count) \
    asm volatile("mbarrier.init.shared.b64 [%0], %1;" :: "r"((uint32_t)(mbar)), "r"((uint32_t)(count)) : "memory")

#define MBARRIER_EXPECT_TX(mbar, bytes) \
    asm volatile("mbarrier.arrive.expect_tx.shared.b64 _, [%0], %1;" \
                 :: "r"((uint32_t)(mbar)), "r"((uint32_t)(bytes)) : "memory")

#define MBARRIER_ARRIVE_CLUSTER(local_mbar, target_rank) \
    asm volatile( \
        "{\n\t.reg .b32 remAddr;\n\t" \
        "mapa.shared::cluster.u32 remAddr, %0, %1;\n\t" \
        "mbarrier.arrive.shared::cluster.b64 _, [remAddr];\n\t}" \
        :: "r"((uint32_t)(local_mbar)), "r"((uint32_t)(target_rank)) : "memory")

#define MBARRIER_WAIT_PARITY(mbar_addr, phase_parity) do {                          \
    uint32_t _mbar = (uint32_t)(mbar_addr);                                         \
    uint32_t _parity = (uint32_t)(phase_parity);                                    \
    uint32_t _done;                                                                 \
    asm volatile(                                                                   \
        "{\n\t.reg .pred p;\n\t"                                                    \
        "mbarrier.try_wait.parity.acquire.cta.shared::cta.b64 p, [%1], %2;\n\t"     \
        "selp.b32 %0, 1, 0, p;\n\t}"                                                \
        : "=r"(_done) : "r"(_mbar), "r"(_parity) : "memory");                       \
    if (!_done) {                                                                   \
        asm volatile(                                                               \
            "{\n\t.reg .pred P1;\n\t"                                               \
            "WAIT_LOOP_%=:\n\t"                                                     \
            "mbarrier.try_wait.parity.acquire.cta.shared::cta.b64 P1, [%0], %1, 0x989680;\n\t" \
            "@P1 bra.uni WAIT_DONE_%=;\n\t"                                         \
            "bra.uni WAIT_LOOP_%=;\n\t"                                             \
            "WAIT_DONE_%=:\n\t}"                                                    \
            :: "r"(_mbar), "r"(_parity) : "memory");                                \
    }                                                                               \
} while (0)

#define TMA_LOAD_3D(smem_addr, tensor_map, cx, cy, cz, mbar) \
    asm volatile( \
        "cp.async.bulk.tensor.3d.shared::cta.global.tile.mbarrier::complete_tx::bytes " \
        "[%0], [%1, {%2, %3, %4}], [%5];" \
        :: "r"((uint32_t)(smem_addr)), "l"(tensor_map), \
           "r"((int32_t)(cx)), "r"((int32_t)(cy)), "r"((int32_t)(cz)), \
           "r"((uint32_t)(mbar)) \
        : "memory")

#define TMA_LOAD_3D_MULTICAST(smem_addr, tensor_map, cx, cy, cz, mbar, cta_mask) \
    asm volatile( \
        "cp.async.bulk.tensor.3d.shared::cluster.global.tile.mbarrier::complete_tx::bytes.multicast::cluster " \
        "[%0], [%1, {%2, %3, %4}], [%5], %6;" \
        :: "r"((uint32_t)(smem_addr)), "l"(tensor_map), \
           "r"((int32_t)(cx)), "r"((int32_t)(cy)), "r"((int32_t)(cz)), \
           "r"((uint32_t)(mbar)), "h"((uint16_t)(cta_mask)) \
        : "memory")

#define CLUSTER_SYNC() do { \
    asm volatile("barrier.cluster.arrive.aligned;" ::: "memory"); \
    asm volatile("barrier.cluster.wait.aligned;" ::: "memory"); \
} while (0)

#define TCGEN05_ALLOC_CG2(smem_result_addr, nCols) \
    asm volatile("tcgen05.alloc.cta_group::2.sync.aligned.shared::cta.b32 [%0], %1;" \
                 :: "r"((uint32_t)(smem_result_addr)), "r"((uint32_t)(nCols)) : "memory")
#define TCGEN05_DEALLOC_CG2(tmem_addr, nCols) \
    asm volatile("tcgen05.dealloc.cta_group::2.sync.aligned.b32 %0, %1;" \
                 :: "r"(tmem_addr), "r"((uint32_t)(nCols)))
#define TCGEN05_RELINQUISH_CG2() \
    asm volatile("tcgen05.relinquish_alloc_permit.cta_group::2.sync.aligned;")
#define TCGEN05_COMMIT_MC_CG2(mbar_addr, cta_mask) \
    asm volatile("tcgen05.commit.cta_group::2.mbarrier::arrive::one.shared::cluster.multicast::cluster.b64 [%0], %1;" \
                 :: "r"((uint32_t)(mbar_addr)), "h"((uint16_t)(cta_mask)) : "memory")
#define TCGEN05_WAIT_LD()  asm volatile("tcgen05.wait::ld.sync.aligned;" ::: "memory")
#define TCGEN05_FENCE_AFTER()  asm volatile("tcgen05.fence::after_thread_sync;" ::: "memory")
#define TCGEN05_FENCE_BEFORE() asm volatile("tcgen05.fence::before_thread_sync;" ::: "memory")

#define TCGEN05_LD_X32(r, tmem_addr) \
    asm volatile( \
        "tcgen05.ld.sync.aligned.32x32b.x32.b32 " \
        "{%0, %1, %2, %3, %4, %5, %6, %7, " \
        " %8, %9, %10, %11, %12, %13, %14, %15, " \
        " %16, %17, %18, %19, %20, %21, %22, %23, " \
        " %24, %25, %26, %27, %28, %29, %30, %31}, [%32];" \
        : "=r"((r)[0]),  "=r"((r)[1]),  "=r"((r)[2]),  "=r"((r)[3]), \
          "=r"((r)[4]),  "=r"((r)[5]),  "=r"((r)[6]),  "=r"((r)[7]), \
          "=r"((r)[8]),  "=r"((r)[9]),  "=r"((r)[10]), "=r"((r)[11]), \
          "=r"((r)[12]), "=r"((r)[13]), "=r"((r)[14]), "=r"((r)[15]), \
          "=r"((r)[16]), "=r"((r)[17]), "=r"((r)[18]), "=r"((r)[19]), \
          "=r"((r)[20]), "=r"((r)[21]), "=r"((r)[22]), "=r"((r)[23]), \
          "=r"((r)[24]), "=r"((r)[25]), "=r"((r)[26]), "=r"((r)[27]), \
          "=r"((r)[28]), "=r"((r)[29]), "=r"((r)[30]), "=r"((r)[31]) \
        : "r"(tmem_addr))

__device__ __forceinline__ uint64_t sdesc_sw128(uint32_t addr) {
    return (2ULL << 61) | (1ULL << 46) | (64ULL << 32) | (1ULL << 16) |
           (uint64_t)((addr >> 4) & 0x3FFF);
}

// idesc kind::f16 cg2: dtype=F32, atype=btype=BF16, N=128, M=256
#define IDESC_CG2 ((1u << 4) | (1u << 7) | (1u << 10) | (16u << 17) | (16u << 24))

__device__ __forceinline__ void mma_f16_ss_cg2(uint32_t d, uint64_t ad, uint64_t bd,
                                               uint32_t idesc, unsigned en) {
    asm volatile(
        "{\n\t.reg .pred p;\n\t"
        "setp.ne.u32 p, %6, 0;\n\t"
        "tcgen05.mma.cta_group::2.kind::f16 [%0], %1, %2, %3, "
        "{%4, %4, %4, %4, %4, %4, %4, %4}, p;\n\t}"
        :: "r"(d), "l"(ad), "l"(bd), "r"(idesc), "r"(0u), "r"(0u), "r"(en) : "memory");
}

#endif // HAS_TCGEN05

// ============================================================================
// PERSISTENT cg2 tcgen05 kernel: 64 CTAs, 16 clusters of 4 (proven R12 base).
// Cross-boundary producer prefetch + dedicated zs + cell state c in REGISTERS
// (fixed tid->element mapping across all GEMMs; c never touches global mem).
// ============================================================================
__global__ __launch_bounds__(256, 1)
void lstm_persist_cg2(const __grid_constant__ CUtensorMap tmx,
                      const __grid_constant__ CUtensorMap tmh1,
                      const __grid_constant__ CUtensorMap tmh2,
                      const __grid_constant__ CUtensorMap tmw1,
                      const __grid_constant__ CUtensorMap tmw2,
                      const float* __restrict__ b1, const float* __restrict__ b2) {
#if HAS_TCGEN05
    extern __shared__ __align__(1024) unsigned char sm[];
    const uint32_t smem_base = smem_u32(sm);
    const int tid = threadIdx.x;
    const int wid = tid >> 5;
    const int lane = tid & 31;

    const int r = (int)(blockIdx.x & 3);
    const int ntg = (int)((blockIdx.x >> 2) * 2 + (r >> 1));
    const int m0 = (r & 1) * 128;
    const int ar = r >> 1;                 // A slice index within same-m pair
    const int leader = ((r & 1) == 0);
    const uint16_t amask = (uint16_t)((1u << r) | (1u << (r ^ 2)));
    const uint16_t pairmask = (uint16_t)(0x3u << (r & ~1));

    const uint32_t ctrl = smem_base + NSTG * STB;          // tmem ptr (16B)
    const uint32_t mb_full = ctrl + 16;
    const uint32_t mb_empty = mb_full + 8 * NSTG;
    const uint32_t mb_done = mb_empty + 8 * NSTG;
    float* zs = (float*)(sm + ZS_OFF);                     // [128][133], dedicated

    if (wid == 0) TCGEN05_ALLOC_CG2(ctrl, 128);
    if (tid == 0) {
#pragma unroll
        for (int s = 0; s < NSTG; s++) {
            MBARRIER_INIT(mb_full + 8 * s, leader ? 2 : 1);
            MBARRIER_INIT(mb_empty + 8 * s, 2);
        }
        MBARRIER_INIT(mb_done, 1);
    }
    __syncthreads();
    CLUSTER_SYNC();
    uint32_t tmem_base;
    asm volatile("ld.shared.b32 %0, [%1];" : "=r"(tmem_base) : "r"(ctrl));

    auto issue_A = [&](int layer_, int t_, int c, uint32_t sbase, uint32_t fb) {
        const int k0 = c * 64;
        const int pin_ = t_ & 1, pout_ = pin_ ^ 1;
        const CUtensorMap* tA;
        int cx, cz;
        if (layer_ == 0) {
            if (k0 < DD) { tA = &tmx;  cx = k0;      cz = t_; }
            else         { tA = &tmh1; cx = k0 - DD; cz = pin_; }
        } else {
            if (k0 < HH) { tA = &tmh1; cx = k0;      cz = pout_; }
            else         { tA = &tmh2; cx = k0 - HH; cz = pin_; }
        }
        TMA_LOAD_3D_MULTICAST(sbase + ar * 8192, tA, cx, m0 + ar * 64, cz, fb, amask);
    };
    auto issue_B = [&](int layer_, int c, uint32_t sbase, uint32_t fb) {
        const CUtensorMap* tB = (layer_ == 0) ? &tmw1 : &tmw2;
        TMA_LOAD_3D(sbase + 16384, tB, c * 64, ntg * 128 + (r & 1) * 64, 0, fb);
    };

    // per-thread persistent cell state (16 fixed elements per layer)
    float c0[16], c1[16];
#pragma unroll
    for (int i = 0; i < 16; i++) { c0[i] = 0.f; c1[i] = 0.f; }

    int done_par = 0;
    unsigned gj = 0;
    unsigned bar_n = 0;
    int pf = 0;       // chunks of CURRENT gemm already issued (producer state)
    int pendA = 0;    // prefetched chunks missing their A part

    for (int t = 0; t < TT; t++) {
#pragma unroll 1
        for (int layer = 0; layer < 2; layer++) {
            const int nc = (layer == 0) ? (K1 / 64) : (K2 / 64);
            const int pout = (t & 1) ^ 1;
            __nv_bfloat16* hout = (layer == 0) ? g_h1[pout] : g_h2[pout];
            const float* bias = (layer == 0) ? b1 : b2;

            if (wid == 1) {
                // ---- producer ----
                if (pendA) {
                    if (elect_one_pred()) {
                        for (int c = 0; c < pf; ++c) {
                            const int s = (int)((gj + (unsigned)c) % NSTG);
                            issue_A(layer, t, c, smem_base + s * STB, mb_full + 8 * s);
                        }
                    }
                    pendA = 0;
                }
                for (int c = pf; c < nc; ++c) {
                    const unsigned G = gj + (unsigned)c;
                    const int s = (int)(G % NSTG);
                    const unsigned n = G / NSTG;
                    if (n > 0) MBARRIER_WAIT_PARITY(mb_empty + 8 * s, (int)((n - 1) & 1));
                    if (elect_one_pred()) {
                        const uint32_t sbase = smem_base + s * STB;
                        const uint32_t fb = mb_full + 8 * s;
                        MBARRIER_EXPECT_TX(fb, (uint32_t)STB);
                        issue_A(layer, t, c, sbase, fb);
                        issue_B(layer, c, sbase, fb);
                    }
                }
                // prefetch next GEMM (overlaps other warps' epilogue)
                if (!(layer == 1 && t == TT - 1)) {
                    const int nlayer = layer ^ 1;
                    const int nt_ = (layer == 0) ? t : t + 1;
                    const int next_nc = (nlayer == 0) ? (K1 / 64) : (K2 / 64);
                    const int npf = (PF < next_nc) ? PF : next_nc;
                    for (int c2 = 0; c2 < npf; ++c2) {
                        const unsigned G = gj + (unsigned)nc + (unsigned)c2;
                        const int s = (int)(G % NSTG);
                        const unsigned n = G / NSTG;
                        if (n > 0) MBARRIER_WAIT_PARITY(mb_empty + 8 * s, (int)((n - 1) & 1));
                        if (elect_one_pred()) {
                            const uint32_t sbase = smem_base + s * STB;
                            const uint32_t fb = mb_full + 8 * s;
                            MBARRIER_EXPECT_TX(fb, (uint32_t)STB);
                            issue_B(nlayer, c2, sbase, fb);
                            if (nlayer == 0) issue_A(nlayer, nt_, c2, sbase, fb);
                        }
                    }
                    pf = npf;
                    pendA = (nlayer == 1);
                } else {
                    pf = 0;
                    pendA = 0;
                }
            } else if (wid == 0) {
                if (leader) {
                    // ---- consumer: cg2 MMA issuer ----
                    for (int c = 0; c < nc; ++c) {
                        const unsigned G = gj + (unsigned)c;
                        const int s = (int)(G % NSTG);
                        const unsigned n = G / NSTG;
                        MBARRIER_WAIT_PARITY(mb_full + 8 * s, (int)(n & 1));
                        if (elect_one_pred()) {
                            const uint64_t ad = sdesc_sw128(smem_base + s * STB);
                            const uint64_t bd = sdesc_sw128(smem_base + s * STB + 16384);
#pragma unroll
                            for (int kk = 0; kk < 4; kk++)
                                mma_f16_ss_cg2(tmem_base, ad + kk * 2, bd + kk * 2,
                                               IDESC_CG2, (unsigned)((c | kk) != 0));
                            TCGEN05_COMMIT_MC_CG2(mb_empty + 8 * s, 0xFu);
                        }
                    }
                    if (elect_one_pred()) TCGEN05_COMMIT_MC_CG2(mb_done, pairmask);
                } else {
                    // ---- odd rank: relay full -> leader ----
                    for (int c = 0; c < nc; ++c) {
                        const unsigned G = gj + (unsigned)c;
                        const int s = (int)(G % NSTG);
                        const unsigned n = G / NSTG;
                        MBARRIER_WAIT_PARITY(mb_full + 8 * s, (int)(n & 1));
                        if (elect_one_pred())
                            MBARRIER_ARRIVE_CLUSTER(mb_full + 8 * s, r - 1);
                    }
                }
            }

            // ---- all warps: wait GEMM completion ----
            MBARRIER_WAIT_PARITY(mb_done, done_par);
            done_par ^= 1;
            TCGEN05_FENCE_AFTER();

            // ---- epilogue: LDTM -> zs -> coalesced cell, c in registers ----
            {
                constexpr int ZSTRIDE = 133;
                const uint32_t cb = (uint32_t)(wid >> 2) * 64;
                const int row = (wid & 3) * 32 + lane;
                uint32_t regs[64];
                TCGEN05_LD_X32(regs, tmem_base + cb);
                TCGEN05_LD_X32(regs + 32, tmem_base + cb + 32);
                TCGEN05_WAIT_LD();
                TCGEN05_FENCE_BEFORE();
#pragma unroll
                for (int c2 = 0; c2 < 64; c2++)
                    zs[row * ZSTRIDE + cb + c2] = __uint_as_float(regs[c2]);
                __syncthreads();

                const int hb = ntg * 32;
                if (layer == 0) {
#pragma unroll
                    for (int i = 0; i < 16; i++) {
                        const int e = tid + 256 * i;
                        const int rr = e >> 5;
                        const int hc = e & 31;
                        float zi = zs[rr * ZSTRIDE + hc]      + bias[hb + hc];
                        float zj = zs[rr * ZSTRIDE + 32 + hc] + bias[HH + hb + hc];
                        float zf = zs[rr * ZSTRIDE + 64 + hc] + bias[2 * HH + hb + hc];
                        float zo = zs[rr * ZSTRIDE + 96 + hc] + bias[3 * HH + hb + hc];
                        float ncell = c0[i] * fast_sigmoid(zf + 1.f) +
                                      fast_sigmoid(zi) * fast_tanh(zj);
                        hout[(m0 + rr) * HH + hb + hc] =
                            __float2bfloat16(fast_tanh(ncell) * fast_sigmoid(zo));
                        c0[i] = ncell;
                    }
                } else {
#pragma unroll
                    for (int i = 0; i < 16; i++) {
                        const int e = tid + 256 * i;
                        const int rr = e >> 5;
                        const int hc = e & 31;
                        float zi = zs[rr * ZSTRIDE + hc]      + bias[hb + hc];
                        float zj = zs[rr * ZSTRIDE + 32 + hc] + bias[HH + hb + hc];
                        float zf = zs[rr * ZSTRIDE + 64 + hc] + bias[2 * HH + hb + hc];
                        float zo = zs[rr * ZSTRIDE + 96 + hc] + bias[3 * HH + hb + hc];
                        float ncell = c1[i] * fast_sigmoid(zf + 1.f) +
                                      fast_sigmoid(zi) * fast_tanh(zj);
                        hout[(m0 + rr) * HH + hb + hc] =
                            __float2bfloat16(fast_tanh(ncell) * fast_sigmoid(zo));
                        c1[i] = ncell;
                    }
                }
            }

            gj += (unsigned)nc;

            // ---- grid barrier ----
            bar_n++;
            __syncthreads();
            if (tid == 0) {
                __threadfence();
                atomicAdd(&g_bar_ctr, 1u);
                const unsigned tgt = bar_n * (unsigned)gridDim.x;
                while (*(volatile unsigned*)&g_bar_ctr < tgt) { }
            }
            __syncthreads();
        }
    }

    CLUSTER_SYNC();
    if (wid == 0) {
        TCGEN05_RELINQUISH_CG2();
        TCGEN05_DEALLOC_CG2(tmem_base, 128);
    }
#endif // HAS_TCGEN05
}

// ============================================================================
// Fallback: mma.sync (HMMA) fused step kernel (round-1 proven path).
// ============================================================================
#define AS_STRIDE 40
#define BS_STRIDE 136
#define ZS_STRIDE 132

__global__ __launch_bounds__(256, 1)
void lstm_step_fb(int layer, int t, int pin, const float* __restrict__ bias) {
    __shared__ __align__(16) unsigned char smem_raw[64 * ZS_STRIDE * 4];
    __nv_bfloat16* As = (__nv_bfloat16*)smem_raw;
    __nv_bfloat16* Bs = (__nv_bfloat16*)(smem_raw + 10240);
    float* zs = (float*)smem_raw;

    int K, boundk, lda0;
    const __nv_bfloat16 *A0, *A1, *Wm;
    float* cst;
    __nv_bfloat16* hout;
    const int pout = pin ^ 1;

    if (layer == 0) {
        K = K1; boundk = DD; lda0 = DD;
        A0 = g_X + (size_t)t * BB * DD;
        A1 = g_h1[pin];
        Wm = g_W1; cst = g_c1; hout = g_h1[pout];
    } else {
        K = K2; boundk = HH; lda0 = HH;
        A0 = g_h1[pout];
        A1 = g_h2[pin];
        Wm = g_W2; cst = g_c2; hout = g_h2[pout];
    }

    const int n0 = blockIdx.x * 32;
    const int m0 = blockIdx.y * 64;
    const int tid = threadIdx.x;
    const int lane = tid & 31;
    const int wid = tid >> 5;
    const int wm = wid & 3;
    const int wn = wid >> 2;
    const int rowA = tid >> 2;
    const int quadA = tid & 3;

    float acc[8][4];
#pragma unroll
    for (int j = 0; j < 8; j++)
#pragma unroll
        for (int q = 0; q < 4; q++) acc[j][q] = 0.f;

    auto load_stage = [&](int kt, int s) {
        const int k0 = kt * 32;
        const __nv_bfloat16* gpA;
        if (k0 < boundk) gpA = A0 + (size_t)(m0 + rowA) * lda0 + k0 + quadA * 8;
        else             gpA = A1 + (size_t)(m0 + rowA) * HH + (k0 - boundk) + quadA * 8;
        uint32_t dstA = smem_u32(As + s * 64 * AS_STRIDE + rowA * AS_STRIDE + quadA * 8);
        asm volatile("cp.async.cg.shared.global [%0], [%1], 16;\n" :: "r"(dstA), "l"(gpA));
#pragma unroll
        for (int i = 0; i < 2; i++) {
            int c = tid + i * 256;
            int kk = c >> 4;
            int ncv = (c & 15) * 8;
            int g = ncv >> 5;
            int col = g * HH + n0 + (ncv & 31);
            const __nv_bfloat16* gpB = Wm + (size_t)(k0 + kk) * FOURH + col;
            uint32_t dstB = smem_u32(Bs + s * 32 * BS_STRIDE + kk * BS_STRIDE + ncv);
            asm volatile("cp.async.cg.shared.global [%0], [%1], 16;\n" :: "r"(dstB), "l"(gpB));
        }
    };

    load_stage(0, 0);
    asm volatile("cp.async.commit_group;\n" ::: "memory");

    const int nK = K >> 5;
    for (int kt = 0; kt < nK; ++kt) {
        const int s = kt & 1;
        if (kt + 1 < nK) load_stage(kt + 1, s ^ 1);
        asm volatile("cp.async.commit_group;\n" ::: "memory");
        asm volatile("cp.async.wait_group 1;\n" ::: "memory");
        __syncthreads();

#pragma unroll
        for (int ks = 0; ks < 2; ++ks) {
            uint32_t a0, a1, a2, a3;
            {
                int row = wm * 16 + (lane & 15);
                int colb = ks * 16 + (lane >> 4) * 8;
                uint32_t addr = smem_u32(As + s * 64 * AS_STRIDE + row * AS_STRIDE + colb);
                asm volatile("ldmatrix.sync.aligned.m8n8.x4.shared.b16 {%0,%1,%2,%3}, [%4];\n"
                             : "=r"(a0), "=r"(a1), "=r"(a2), "=r"(a3) : "r"(addr));
            }
#pragma unroll
            for (int j2 = 0; j2 < 4; j2++) {
                uint32_t b0, b1, b2, b3;
                int krow = ks * 16 + (lane & 7) + ((lane >> 3) & 1) * 8;
                int ncol = wn * 64 + j2 * 16 + (lane >> 4) * 8;
                uint32_t addr = smem_u32(Bs + s * 32 * BS_STRIDE + krow * BS_STRIDE + ncol);
                asm volatile("ldmatrix.sync.aligned.m8n8.x4.trans.shared.b16 {%0,%1,%2,%3}, [%4];\n"
                             : "=r"(b0), "=r"(b1), "=r"(b2), "=r"(b3) : "r"(addr));
                asm volatile("mma.sync.aligned.m16n8k16.row.col.f32.bf16.bf16.f32 "
                             "{%0,%1,%2,%3}, {%4,%5,%6,%7}, {%8,%9}, {%0,%1,%2,%3};\n"
                             : "+f"(acc[2 * j2][0]), "+f"(acc[2 * j2][1]),
                               "+f"(acc[2 * j2][2]), "+f"(acc[2 * j2][3])
                             : "r"(a0), "r"(a1), "r"(a2), "r"(a3), "r"(b0), "r"(b1));
                asm volatile("mma.sync.aligned.m16n8k16.row.col.f32.bf16.bf16.f32 "
                             "{%0,%1,%2,%3}, {%4,%5,%6,%7}, {%8,%9}, {%0,%1,%2,%3};\n"
                             : "+f"(acc[2 * j2 + 1][0]), "+f"(acc[2 * j2 + 1][1]),
                               "+f"(acc[2 * j2 + 1][2]), "+f"(acc[2 * j2 + 1][3])
                             : "r"(a0), "r"(a1), "r"(a2), "r"(a3), "r"(b2), "r"(b3));
            }
        }
        __syncthreads();
    }

#pragma unroll
    for (int j = 0; j < 8; j++) {
        int col = wn * 64 + j * 8 + (lane & 3) * 2;
        int rr = wm * 16 + (lane >> 2);
        zs[rr * ZS_STRIDE + col]           = acc[j][0];
        zs[rr * ZS_STRIDE + col + 1]       = acc[j][1];
        zs[(rr + 8) * ZS_STRIDE + col]     = acc[j][2];
        zs[(rr + 8) * ZS_STRIDE + col + 1] = acc[j][3];
    }
    __syncthreads();

#pragma unroll
    for (int e = tid; e < 64 * 32; e += 256) {
        int rr = e >> 5;
        int hc = e & 31;
        float zi = zs[rr * ZS_STRIDE + hc]        + bias[0 * HH + n0 + hc];
        float zj = zs[rr * ZS_STRIDE + 32 + hc]   + bias[1 * HH + n0 + hc];
        float zf = zs[rr * ZS_STRIDE + 64 + hc]   + bias[2 * HH + n0 + hc];
        float zo = zs[rr * ZS_STRIDE + 96 + hc]   + bias[3 * HH + n0 + hc];
        int gi = (m0 + rr) * HH + n0 + hc;
        float c = cst[gi];
        float ncell = c * sigmoidf_(zf + 1.f) + sigmoidf_(zi) * tanhf(zj);
        float nh = tanhf(ncell) * sigmoidf_(zo);
        cst[gi] = ncell;
        hout[gi] = __float2bfloat16(nh);
    }
}

// ---------------- dense head + loss ----------------
__global__ void head_kernel(const float* __restrict__ Wd, const float* __restrict__ bd,
                            const float* __restrict__ labels) {
    const int b = blockIdx.x;
    const int lane = threadIdx.x & 31;
    const int w = threadIdx.x >> 5;
    const __nv_bfloat16* h = g_h2[0];  // T=336 even -> final h2 in slot 0
    __shared__ float warpsum[8];
    float total = 0.f;
    for (int l = w; l < 24; l += 8) {
        float s = 0.f;
        for (int k = lane; k < HH; k += 32)
            s += __bfloat162float(h[b * HH + k]) * Wd[k * 24 + l];
#pragma unroll
        for (int off = 16; off; off >>= 1) s += __shfl_xor_sync(0xffffffffu, s, off);
        if (lane == 0) {
            float pred = s + bd[l];
            float e = pred - labels[b * 24 + l];
            total += e * e;
        }
    }
    if (lane == 0) warpsum[w] = total;
    __syncthreads();
    if (threadIdx.x == 0) {
        float acc = 0.f;
#pragma unroll
        for (int i = 0; i < 8; i++) acc += warpsum[i];
        g_partial[b] = acc;
    }
}

__global__ void finish_kernel(float* __restrict__ out) {
    __shared__ float sh[256];
    sh[threadIdx.x] = g_partial[threadIdx.x];
    __syncthreads();
    for (int s = 128; s; s >>= 1) {
        if (threadIdx.x < s) sh[threadIdx.x] += sh[threadIdx.x + s];
        __syncthreads();
    }
    if (threadIdx.x == 0) out[0] = sh[0] / (float)(BB * 24);
}

// ---------------- host: tensormap encoding ----------------
typedef CUresult (*encode_fn_t)(
    CUtensorMap*, CUtensorMapDataType, cuuint32_t, void*,
    const cuuint64_t*, const cuuint64_t*, const cuuint32_t*, const cuuint32_t*,
    CUtensorMapInterleave, CUtensorMapSwizzle, CUtensorMapL2promotion,
    CUtensorMapFloatOOBfill);

static bool encode_map(encode_fn_t enc, CUtensorMap* tm, void* base,
                       uint64_t d0, uint64_t d1, uint64_t d2,
                       uint64_t s1_bytes, uint64_t s2_bytes) {
    cuuint64_t dims[3] = {d0, d1, d2};
    cuuint64_t strides[2] = {s1_bytes, s2_bytes};
    cuuint32_t box[3] = {64, 64, 1};
    cuuint32_t es[3] = {1, 1, 1};
    CUresult res = enc(tm, CU_TENSOR_MAP_DATA_TYPE_BFLOAT16, 3, base,
                       dims, strides, box, es,
                       CU_TENSOR_MAP_INTERLEAVE_NONE, CU_TENSOR_MAP_SWIZZLE_128B,
                       CU_TENSOR_MAP_L2_PROMOTION_L2_128B,
                       CU_TENSOR_MAP_FLOAT_OOB_FILL_NONE);
    return res == CUDA_SUCCESS;
}

// ---------------- launch ----------------
extern "C" void kernel_launch(void* const* d_in, const int* in_sizes, int n_in,
                              void* d_out, int out_size) {
    const float* features = (const float*)d_in[0];
    const float* labels   = (const float*)d_in[1];
    const float* W1       = (const float*)d_in[2];
    const float* b1       = (const float*)d_in[3];
    const float* W2       = (const float*)d_in[4];
    const float* b2       = (const float*)d_in[5];
    const float* Wd       = (const float*)d_in[6];
    const float* bd       = (const float*)d_in[7];
    float* out = (float*)d_out;

    static CUtensorMap tmx, tmh1, tmh2, tmw1, tmw2;
    static int mode = -1;   // 0 = mma.sync fallback, 1 = cg2 persistent
    if (mode < 0) {
        mode = 0;
        cudaFuncAttributes attr{};
        cudaFuncGetAttributes(&attr, lstm_persist_cg2);
        if (attr.numRegs > 40) {
            void* fp = nullptr;
            cudaDriverEntryPointQueryResult qr = cudaDriverEntryPointSuccess;
            cudaGetDriverEntryPointByVersion("cuTensorMapEncodeTiled", &fp, 12000,
                                             cudaEnableDefault, &qr);
            void *px = nullptr, *ph1 = nullptr, *ph2 = nullptr, *pw1 = nullptr, *pw2 = nullptr;
            cudaGetSymbolAddress(&px, g_X);
            cudaGetSymbolAddress(&ph1, g_h1);
            cudaGetSymbolAddress(&ph2, g_h2);
            cudaGetSymbolAddress(&pw1, g_W1);
            cudaGetSymbolAddress(&pw2, g_W2);
            if (fp && px && ph1 && ph2 && pw1 && pw2) {
                encode_fn_t enc = (encode_fn_t)fp;
                bool ok = true;
                ok &= encode_map(enc, &tmx,  px,  DD, BB, TT, (uint64_t)DD * 2, (uint64_t)BB * DD * 2);
                ok &= encode_map(enc, &tmh1, ph1, HH, BB, 2,  (uint64_t)HH * 2, (uint64_t)BB * HH * 2);
                ok &= encode_map(enc, &tmh2, ph2, HH, BB, 2,  (uint64_t)HH * 2, (uint64_t)BB * HH * 2);
                ok &= encode_map(enc, &tmw1, pw1, K1, FOURH, 1, (uint64_t)K1 * 2, (uint64_t)K1 * FOURH * 2);
                ok &= encode_map(enc, &tmw2, pw2, K2, FOURH, 1, (uint64_t)K2 * 2, (uint64_t)K2 * FOURH * 2);
                if (ok && cudaFuncSetAttribute(lstm_persist_cg2,
                        cudaFuncAttributeMaxDynamicSharedMemorySize, SMEM_CG2) == cudaSuccess) {
                    mode = 1;
                }
            }
        }
    }

    if (mode == 1) {
        conv_w_t<<<dim3(K1 / 32, 32, 4), dim3(32, 8)>>>(W1, 0, K1);
        conv_w_t<<<dim3(K2 / 32, 32, 4), dim3(32, 8)>>>(W2, 1, K2);
    } else {
        conv_w_kernel<<<592, 256>>>(W1, 0, K1 * FOURH);
        conv_w_kernel<<<592, 256>>>(W2, 1, K2 * FOURH);
    }
    conv_x_kernel<<<592, 256>>>(features);
    init_state_kernel<<<512, 256>>>();

    if (mode == 1) {
        cudaLaunchConfig_t cfg = {};
        cfg.gridDim = dim3(NCTA, 1, 1);
        cfg.blockDim = dim3(256, 1, 1);
        cfg.dynamicSmemBytes = SMEM_CG2;
        cudaLaunchAttribute at[1];
        at[0].id = cudaLaunchAttributeClusterDimension;
        at[0].val.clusterDim = {4, 1, 1};
        cfg.attrs = at;
        cfg.numAttrs = 1;
        cudaLaunchKernelEx(&cfg, lstm_persist_cg2, tmx, tmh1, tmh2, tmw1, tmw2, b1, b2);
    } else {
        dim3 grid(32, 4);
        for (int t = 0; t < TT; t++) {
            int p = t & 1;
            lstm_step_fb<<<grid, 256>>>(0, t, p, b1);
            lstm_step_fb<<<grid, 256>>>(1, t, p, b2);
        }
    }

    head_kernel<<<BB, 256>>>(Wd, bd, labels);
    finish_kernel<<<1, 256>>>(out);
}

// round 16
// speedup vs baseline: 1.8838x; 1.0800x over previous
#include <cuda_runtime.h>
#include <cuda.h>
#include <cuda_bf16.h>
#include <cstdint>

#define BB 256
#define TT 336
#define DD 128
#define HH 1024
#define K1 1152
#define K2 2048
#define FOURH 4096

#define NSTG 6
#define PF 4

// ---- arch-feature gate ----
#if defined(__CUDA_ARCH__) && \
    (defined(__CUDA_ARCH_FEAT_SM103_ALL) || defined(__CUDA_ARCH_FEAT_SM100_ALL) || \
     (defined(__CUDA_ARCH_SPECIFIC__) && (__CUDA_ARCH_SPECIFIC__ >= 1000)) || \
     (defined(__CUDA_ARCH_FAMILY_SPECIFIC__) && (__CUDA_ARCH_FAMILY_SPECIFIC__ >= 1000)))
#define HAS_TCGEN05 1
#else
#define HAS_TCGEN05 0
#endif

// ---------------- device-global scratch ----------------
// tc layout: Wp[(w/gw)*(4*gw) + g*gw + (w%gw)][K]  (gw = NTILE/4)
__device__ __nv_bfloat16 g_W1[K1 * FOURH];
__device__ __nv_bfloat16 g_W2[K2 * FOURH];
__device__ __nv_bfloat16 g_X[TT * BB * DD];  // [t][b][d]
__device__ __nv_bfloat16 g_h1[2][BB * HH];
__device__ __nv_bfloat16 g_h2[2][BB * HH];
__device__ float g_c1[BB * HH];              // fallback path only
__device__ float g_c2[BB * HH];
__device__ float g_partial[BB];
__device__ unsigned g_bar_ctr;

// ---------------- helpers ----------------
__device__ __forceinline__ uint32_t smem_u32(const void* p) {
    return (uint32_t)__cvta_generic_to_shared(p);
}
__device__ __forceinline__ float fast_tanh(float x) {
    float y;
    asm("tanh.approx.f32 %0, %1;" : "=f"(y) : "f"(x));
    return y;
}
__device__ __forceinline__ float fast_sigmoid(float x) {
    return 0.5f * fast_tanh(0.5f * x) + 0.5f;
}
__device__ __forceinline__ float sigmoidf_(float x) { return 1.f / (1.f + __expf(-x)); }

// ---------------- conversion / init kernels ----------------
// tc path: W[k][4096] fp32 -> Wp[(w/gw)*(4*gw) + g*gw + (w%gw)][K] bf16
__global__ void conv_w_t(const float* __restrict__ src, int which, int K, int gw) {
    __shared__ float tile[32][33];
    const int kb = blockIdx.x * 32, wb = blockIdx.y * 32, g = blockIdx.z;
    const int tx = threadIdx.x, ty0 = threadIdx.y;
    const int ntile = 4 * gw;
#pragma unroll
    for (int i = 0; i < 4; i++) {
        int ty = ty0 + i * 8;
        tile[ty][tx] = src[(size_t)(kb + ty) * FOURH + g * HH + wb + tx];
    }
    __syncthreads();
    __nv_bfloat16* dst = (which == 0) ? g_W1 : g_W2;
#pragma unroll
    for (int i = 0; i < 4; i++) {
        int ty = ty0 + i * 8;
        int w = wb + ty;
        int row = (w / gw) * ntile + g * gw + (w % gw);
        dst[(size_t)row * K + kb + tx] = __float2bfloat16(tile[tx][ty]);
    }
}

__global__ void conv_w_kernel(const float* __restrict__ src, int which, int n) {
    for (int i = blockIdx.x * blockDim.x + threadIdx.x; i < n; i += gridDim.x * blockDim.x) {
        __nv_bfloat16 v = __float2bfloat16(src[i]);
        if (which == 0) g_W1[i] = v;
        else            g_W2[i] = v;
    }
}

__global__ void conv_x_kernel(const float* __restrict__ f) {
    int n = BB * TT * DD;
    for (int i = blockIdx.x * blockDim.x + threadIdx.x; i < n; i += gridDim.x * blockDim.x) {
        int b = i / (TT * DD);
        int r = i % (TT * DD);
        int t = r / DD;
        int d = r % DD;
        g_X[(size_t)t * BB * DD + b * DD + d] = __float2bfloat16(f[i]);
    }
}

__global__ void init_state_kernel() {
    int n = BB * HH;
    __nv_bfloat16 z = __float2bfloat16(0.f);
    if (blockIdx.x == 0 && threadIdx.x == 0) g_bar_ctr = 0;
    for (int i = blockIdx.x * blockDim.x + threadIdx.x; i < n; i += gridDim.x * blockDim.x) {
        g_c1[i] = 0.f;
        g_c2[i] = 0.f;
        g_h1[0][i] = z;
        g_h2[0][i] = z;
    }
}

// ============================================================================
// tcgen05 + TMA PTX helpers ('a'-variant targets only)
// ============================================================================
#if HAS_TCGEN05

__device__ __forceinline__ uint32_t elect_one_pred() {
    uint32_t pred;
    asm volatile(
        "{\n\t.reg .pred p;\n\t"
        "elect.sync _|p, 0xFFFFFFFF;\n\t"
        "selp.b32 %0, 1, 0, p;\n\t}"
        : "=r"(pred));
    return pred;
}

#define MBARRIER_INIT(mbar, count) \
    asm volatile("mbarrier.init.shared.b64 [%0], %1;" :: "r"((uint32_t)(mbar)), "r"((uint32_t)(count)) : "memory")

#define MBARRIER_EXPECT_TX(mbar, bytes) \
    asm volatile("mbarrier.arrive.expect_tx.shared.b64 _, [%0], %1;" \
                 :: "r"((uint32_t)(mbar)), "r"((uint32_t)(bytes)) : "memory")

#define MBARRIER_ARRIVE_CLUSTER(local_mbar, target_rank) \
    asm volatile( \
        "{\n\t.reg .b32 remAddr;\n\t" \
        "mapa.shared::cluster.u32 remAddr, %0, %1;\n\t" \
        "mbarrier.arrive.shared::cluster.b64 _, [remAddr];\n\t}" \
        :: "r"((uint32_t)(local_mbar)), "r"((uint32_t)(target_rank)) : "memory")

#define MBARRIER_WAIT_PARITY(mbar_addr, phase_parity) do {                          \
    uint32_t _mbar = (uint32_t)(mbar_addr);                                         \
    uint32_t _parity = (uint32_t)(phase_parity);                                    \
    uint32_t _done;                                                                 \
    asm volatile(                                                                   \
        "{\n\t.reg .pred p;\n\t"                                                    \
        "mbarrier.try_wait.parity.acquire.cta.shared::cta.b64 p, [%1], %2;\n\t"     \
        "selp.b32 %0, 1, 0, p;\n\t}"                                                \
        : "=r"(_done) : "r"(_mbar), "r"(_parity) : "memory");                       \
    if (!_done) {                                                                   \
        asm volatile(                                                               \
            "{\n\t.reg .pred P1;\n\t"                                               \
            "WAIT_LOOP_%=:\n\t"                                                     \
            "mbarrier.try_wait.parity.acquire.cta.shared::cta.b64 P1, [%0], %1, 0x989680;\n\t" \
            "@P1 bra.uni WAIT_DONE_%=;\n\t"                                         \
            "bra.uni WAIT_LOOP_%=;\n\t"                                             \
            "WAIT_DONE_%=:\n\t}"                                                    \
            :: "r"(_mbar), "r"(_parity) : "memory");                                \
    }                                                                               \
} while (0)

#define TMA_LOAD_3D(smem_addr, tensor_map, cx, cy, cz, mbar) \
    asm volatile( \
        "cp.async.bulk.tensor.3d.shared::cta.global.tile.mbarrier::complete_tx::bytes " \
        "[%0], [%1, {%2, %3, %4}], [%5];" \
        :: "r"((uint32_t)(smem_addr)), "l"(tensor_map), \
           "r"((int32_t)(cx)), "r"((int32_t)(cy)), "r"((int32_t)(cz)), \
           "r"((uint32_t)(mbar)) \
        : "memory")

#define TMA_LOAD_3D_MULTICAST(smem_addr, tensor_map, cx, cy, cz, mbar, cta_mask) \
    asm volatile( \
        "cp.async.bulk.tensor.3d.shared::cluster.global.tile.mbarrier::complete_tx::bytes.multicast::cluster " \
        "[%0], [%1, {%2, %3, %4}], [%5], %6;" \
        :: "r"((uint32_t)(smem_addr)), "l"(tensor_map), \
           "r"((int32_t)(cx)), "r"((int32_t)(cy)), "r"((int32_t)(cz)), \
           "r"((uint32_t)(mbar)), "h"((uint16_t)(cta_mask)) \
        : "memory")

#define CLUSTER_SYNC() do { \
    asm volatile("barrier.cluster.arrive.aligned;" ::: "memory"); \
    asm volatile("barrier.cluster.wait.aligned;" ::: "memory"); \
} while (0)

#define TCGEN05_ALLOC_CG2(smem_result_addr, nCols) \
    asm volatile("tcgen05.alloc.cta_group::2.sync.aligned.shared::cta.b32 [%0], %1;" \
                 :: "r"((uint32_t)(smem_result_addr)), "r"((uint32_t)(nCols)) : "memory")
#define TCGEN05_DEALLOC_CG2(tmem_addr, nCols) \
    asm volatile("tcgen05.dealloc.cta_group::2.sync.aligned.b32 %0, %1;" \
                 :: "r"(tmem_addr), "r"((uint32_t)(nCols)))
#define TCGEN05_RELINQUISH_CG2() \
    asm volatile("tcgen05.relinquish_alloc_permit.cta_group::2.sync.aligned;")
#define TCGEN05_COMMIT_MC_CG2(mbar_addr, cta_mask) \
    asm volatile("tcgen05.commit.cta_group::2.mbarrier::arrive::one.shared::cluster.multicast::cluster.b64 [%0], %1;" \
                 :: "r"((uint32_t)(mbar_addr)), "h"((uint16_t)(cta_mask)) : "memory")
#define TCGEN05_WAIT_LD()  asm volatile("tcgen05.wait::ld.sync.aligned;" ::: "memory")
#define TCGEN05_FENCE_AFTER()  asm volatile("tcgen05.fence::after_thread_sync;" ::: "memory")
#define TCGEN05_FENCE_BEFORE() asm volatile("tcgen05.fence::before_thread_sync;" ::: "memory")

#define TCGEN05_LD_X32(r, tmem_addr) \
    asm volatile( \
        "tcgen05.ld.sync.aligned.32x32b.x32.b32 " \
        "{%0, %1, %2, %3, %4, %5, %6, %7, " \
        " %8, %9, %10, %11, %12, %13, %14, %15, " \
        " %16, %17, %18, %19, %20, %21, %22, %23, " \
        " %24, %25, %26, %27, %28, %29, %30, %31}, [%32];" \
        : "=r"((r)[0]),  "=r"((r)[1]),  "=r"((r)[2]),  "=r"((r)[3]), \
          "=r"((r)[4]),  "=r"((r)[5]),  "=r"((r)[6]),  "=r"((r)[7]), \
          "=r"((r)[8]),  "=r"((r)[9]),  "=r"((r)[10]), "=r"((r)[11]), \
          "=r"((r)[12]), "=r"((r)[13]), "=r"((r)[14]), "=r"((r)[15]), \
          "=r"((r)[16]), "=r"((r)[17]), "=r"((r)[18]), "=r"((r)[19]), \
          "=r"((r)[20]), "=r"((r)[21]), "=r"((r)[22]), "=r"((r)[23]), \
          "=r"((r)[24]), "=r"((r)[25]), "=r"((r)[26]), "=r"((r)[27]), \
          "=r"((r)[28]), "=r"((r)[29]), "=r"((r)[30]), "=r"((r)[31]) \
        : "r"(tmem_addr))

__device__ __forceinline__ uint64_t sdesc_sw128(uint32_t addr) {
    return (2ULL << 61) | (1ULL << 46) | (64ULL << 32) | (1ULL << 16) |
           (uint64_t)((addr >> 4) & 0x3FFF);
}

__device__ __forceinline__ void mma_f16_ss_cg2(uint32_t d, uint64_t ad, uint64_t bd,
                                               uint32_t idesc, unsigned en) {
    asm volatile(
        "{\n\t.reg .pred p;\n\t"
        "setp.ne.u32 p, %6, 0;\n\t"
        "tcgen05.mma.cta_group::2.kind::f16 [%0], %1, %2, %3, "
        "{%4, %4, %4, %4, %4, %4, %4, %4}, p;\n\t}"
        :: "r"(d), "l"(ad), "l"(bd), "r"(idesc), "r"(0u), "r"(0u), "r"(en) : "memory");
}

#endif // HAS_TCGEN05

// ============================================================================
// PERSISTENT cg2 tcgen05 kernel, templated over N-tile:
//   <128>: 64 CTAs / 16 clusters of 4 (the 4568us champion, byte-equivalent).
//   <64> : 128 CTAs / 32 clusters of 4 — halves per-SM MMA floor. Coalesced
//          zs epilogue + register c (fixes R9's uncoalesced-epilogue 55ms).
// Cluster rank r: m0=(r&1)*128, nt_local=r>>1. A multicast {r, r^2}; B own half.
// ============================================================================
template <int NTILE>
__global__ __launch_bounds__(256, 1)
void lstm_persist_cg2(const __grid_constant__ CUtensorMap tmx,
                      const __grid_constant__ CUtensorMap tmh1,
                      const __grid_constant__ CUtensorMap tmh2,
                      const __grid_constant__ CUtensorMap tmw1,
                      const __grid_constant__ CUtensorMap tmw2,
                      const float* __restrict__ b1, const float* __restrict__ b2) {
#if HAS_TCGEN05
    constexpr int STB = 16384 + (NTILE / 2) * 128;     // A 16KB + B half-tile
    constexpr int ZSTRIDE = (NTILE == 128) ? 133 : 69;
    constexpr int HW = NTILE / 4;                       // h-cols per CTA
    constexpr int CE = 128 * HW / 256;                  // cell elems per thread
    constexpr uint32_t IDESC =
        (1u << 4) | (1u << 7) | (1u << 10) | ((NTILE / 8u) << 17) | (16u << 24);

    extern __shared__ __align__(1024) unsigned char sm[];
    const uint32_t smem_base = smem_u32(sm);
    const int tid = threadIdx.x;
    const int wid = tid >> 5;
    const int lane = tid & 31;

    const int r = (int)(blockIdx.x & 3);
    const int ntg = (int)((blockIdx.x >> 2) * 2 + (r >> 1));
    const int m0 = (r & 1) * 128;
    const int ar = r >> 1;
    const int leader = ((r & 1) == 0);
    const uint16_t amask = (uint16_t)((1u << r) | (1u << (r ^ 2)));
    const uint16_t pairmask = (uint16_t)(0x3u << (r & ~1));

    const uint32_t ctrl = smem_base + NSTG * STB;       // tmem ptr (16B)
    const uint32_t mb_full = ctrl + 16;
    const uint32_t mb_empty = mb_full + 8 * NSTG;
    const uint32_t mb_done = mb_empty + 8 * NSTG;
    float* zs = (float*)(sm + NSTG * STB + 1024);       // dedicated region

    if (wid == 0) TCGEN05_ALLOC_CG2(ctrl, NTILE);
    if (tid == 0) {
#pragma unroll
        for (int s = 0; s < NSTG; s++) {
            MBARRIER_INIT(mb_full + 8 * s, leader ? 2 : 1);
            MBARRIER_INIT(mb_empty + 8 * s, 2);
        }
        MBARRIER_INIT(mb_done, 1);
    }
    __syncthreads();
    CLUSTER_SYNC();
    uint32_t tmem_base;
    asm volatile("ld.shared.b32 %0, [%1];" : "=r"(tmem_base) : "r"(ctrl));

    auto issue_A = [&](int layer_, int t_, int c, uint32_t sbase, uint32_t fb) {
        const int k0 = c * 64;
        const int pin_ = t_ & 1, pout_ = pin_ ^ 1;
        const CUtensorMap* tA;
        int cx, cz;
        if (layer_ == 0) {
            if (k0 < DD) { tA = &tmx;  cx = k0;      cz = t_; }
            else         { tA = &tmh1; cx = k0 - DD; cz = pin_; }
        } else {
            if (k0 < HH) { tA = &tmh1; cx = k0;      cz = pout_; }
            else         { tA = &tmh2; cx = k0 - HH; cz = pin_; }
        }
        TMA_LOAD_3D_MULTICAST(sbase + ar * 8192, tA, cx, m0 + ar * 64, cz, fb, amask);
    };
    auto issue_B = [&](int layer_, int c, uint32_t sbase, uint32_t fb) {
        const CUtensorMap* tB = (layer_ == 0) ? &tmw1 : &tmw2;
        TMA_LOAD_3D(sbase + 16384, tB, c * 64,
                    ntg * NTILE + (r & 1) * (NTILE / 2), 0, fb);
    };

    // per-thread persistent cell state (fixed elements per layer)
    float c0[CE], c1[CE];
#pragma unroll
    for (int i = 0; i < CE; i++) { c0[i] = 0.f; c1[i] = 0.f; }

    int done_par = 0;
    unsigned gj = 0;
    unsigned bar_n = 0;
    int pf = 0;
    int pendA = 0;

    for (int t = 0; t < TT; t++) {
#pragma unroll 1
        for (int layer = 0; layer < 2; layer++) {
            const int nc = (layer == 0) ? (K1 / 64) : (K2 / 64);
            const int pout = (t & 1) ^ 1;
            __nv_bfloat16* hout = (layer == 0) ? g_h1[pout] : g_h2[pout];
            const float* bias = (layer == 0) ? b1 : b2;

            if (wid == 1) {
                // ---- producer ----
                if (pendA) {
                    if (elect_one_pred()) {
                        for (int c = 0; c < pf; ++c) {
                            const int s = (int)((gj + (unsigned)c) % NSTG);
                            issue_A(layer, t, c, smem_base + s * STB, mb_full + 8 * s);
                        }
                    }
                    pendA = 0;
                }
                for (int c = pf; c < nc; ++c) {
                    const unsigned G = gj + (unsigned)c;
                    const int s = (int)(G % NSTG);
                    const unsigned n = G / NSTG;
                    if (n > 0) MBARRIER_WAIT_PARITY(mb_empty + 8 * s, (int)((n - 1) & 1));
                    if (elect_one_pred()) {
                        const uint32_t sbase = smem_base + s * STB;
                        const uint32_t fb = mb_full + 8 * s;
                        MBARRIER_EXPECT_TX(fb, (uint32_t)STB);
                        issue_A(layer, t, c, sbase, fb);
                        issue_B(layer, c, sbase, fb);
                    }
                }
                // prefetch next GEMM (overlaps other warps' epilogue)
                if (!(layer == 1 && t == TT - 1)) {
                    const int nlayer = layer ^ 1;
                    const int nt_ = (layer == 0) ? t : t + 1;
                    const int next_nc = (nlayer == 0) ? (K1 / 64) : (K2 / 64);
                    const int npf = (PF < next_nc) ? PF : next_nc;
                    for (int c2 = 0; c2 < npf; ++c2) {
                        const unsigned G = gj + (unsigned)nc + (unsigned)c2;
                        const int s = (int)(G % NSTG);
                        const unsigned n = G / NSTG;
                        if (n > 0) MBARRIER_WAIT_PARITY(mb_empty + 8 * s, (int)((n - 1) & 1));
                        if (elect_one_pred()) {
                            const uint32_t sbase = smem_base + s * STB;
                            const uint32_t fb = mb_full + 8 * s;
                            MBARRIER_EXPECT_TX(fb, (uint32_t)STB);
                            issue_B(nlayer, c2, sbase, fb);
                            if (nlayer == 0) issue_A(nlayer, nt_, c2, sbase, fb);
                        }
                    }
                    pf = npf;
                    pendA = (nlayer == 1);
                } else {
                    pf = 0;
                    pendA = 0;
                }
            } else if (wid == 0) {
                if (leader) {
                    // ---- consumer: cg2 MMA issuer ----
                    for (int c = 0; c < nc; ++c) {
                        const unsigned G = gj + (unsigned)c;
                        const int s = (int)(G % NSTG);
                        const unsigned n = G / NSTG;
                        MBARRIER_WAIT_PARITY(mb_full + 8 * s, (int)(n & 1));
                        if (elect_one_pred()) {
                            const uint64_t ad = sdesc_sw128(smem_base + s * STB);
                            const uint64_t bd = sdesc_sw128(smem_base + s * STB + 16384);
#pragma unroll
                            for (int kk = 0; kk < 4; kk++)
                                mma_f16_ss_cg2(tmem_base, ad + kk * 2, bd + kk * 2,
                                               IDESC, (unsigned)((c | kk) != 0));
                            TCGEN05_COMMIT_MC_CG2(mb_empty + 8 * s, 0xFu);
                        }
                    }
                    if (elect_one_pred()) TCGEN05_COMMIT_MC_CG2(mb_done, pairmask);
                } else {
                    // ---- odd rank: relay full -> leader ----
                    for (int c = 0; c < nc; ++c) {
                        const unsigned G = gj + (unsigned)c;
                        const int s = (int)(G % NSTG);
                        const unsigned n = G / NSTG;
                        MBARRIER_WAIT_PARITY(mb_full + 8 * s, (int)(n & 1));
                        if (elect_one_pred())
                            MBARRIER_ARRIVE_CLUSTER(mb_full + 8 * s, r - 1);
                    }
                }
            }

            // ---- all warps: wait GEMM completion ----
            MBARRIER_WAIT_PARITY(mb_done, done_par);
            done_par ^= 1;
            TCGEN05_FENCE_AFTER();

            // ---- epilogue: LDTM -> zs -> coalesced cell, c in registers ----
            {
                const uint32_t cb = (uint32_t)(wid >> 2) * (NTILE / 2);
                const int row = (wid & 3) * 32 + lane;
                if constexpr (NTILE == 128) {
                    uint32_t regs[64];
                    TCGEN05_LD_X32(regs, tmem_base + cb);
                    TCGEN05_LD_X32(regs + 32, tmem_base + cb + 32);
                    TCGEN05_WAIT_LD();
                    TCGEN05_FENCE_BEFORE();
#pragma unroll
                    for (int c2 = 0; c2 < 64; c2++)
                        zs[row * ZSTRIDE + cb + c2] = __uint_as_float(regs[c2]);
                } else {
                    uint32_t regs[32];
                    TCGEN05_LD_X32(regs, tmem_base + cb);
                    TCGEN05_WAIT_LD();
                    TCGEN05_FENCE_BEFORE();
#pragma unroll
                    for (int c2 = 0; c2 < 32; c2++)
                        zs[row * ZSTRIDE + cb + c2] = __uint_as_float(regs[c2]);
                }
                __syncthreads();

                const int hb = ntg * HW;
                float* cc = (layer == 0) ? c0 : c1;
#pragma unroll
                for (int i = 0; i < CE; i++) {
                    const int e = tid + 256 * i;
                    const int rr = e / HW;
                    const int hc = e % HW;
                    float zi = zs[rr * ZSTRIDE + hc]          + bias[hb + hc];
                    float zj = zs[rr * ZSTRIDE + HW + hc]     + bias[HH + hb + hc];
                    float zf = zs[rr * ZSTRIDE + 2 * HW + hc] + bias[2 * HH + hb + hc];
                    float zo = zs[rr * ZSTRIDE + 3 * HW + hc] + bias[3 * HH + hb + hc];
                    float ncell = cc[i] * fast_sigmoid(zf + 1.f) +
                                  fast_sigmoid(zi) * fast_tanh(zj);
                    hout[(m0 + rr) * HH + hb + hc] =
                        __float2bfloat16(fast_tanh(ncell) * fast_sigmoid(zo));
                    cc[i] = ncell;
                }
            }

            gj += (unsigned)nc;

            // ---- grid barrier ----
            bar_n++;
            __syncthreads();
            if (tid == 0) {
                __threadfence();
                atomicAdd(&g_bar_ctr, 1u);
                const unsigned tgt = bar_n * (unsigned)gridDim.x;
                while (*(volatile unsigned*)&g_bar_ctr < tgt) { }
            }
            __syncthreads();
        }
    }

    CLUSTER_SYNC();
    if (wid == 0) {
        TCGEN05_RELINQUISH_CG2();
        TCGEN05_DEALLOC_CG2(tmem_base, NTILE);
    }
#endif // HAS_TCGEN05
}

// ============================================================================
// Fallback: mma.sync (HMMA) fused step kernel (round-1 proven path).
// ============================================================================
#define AS_STRIDE 40
#define BS_STRIDE 136
#define ZS_STRIDE 132

__global__ __launch_bounds__(256, 1)
void lstm_step_fb(int layer, int t, int pin, const float* __restrict__ bias) {
    __shared__ __align__(16) unsigned char smem_raw[64 * ZS_STRIDE * 4];
    __nv_bfloat16* As = (__nv_bfloat16*)smem_raw;
    __nv_bfloat16* Bs = (__nv_bfloat16*)(smem_raw + 10240);
    float* zs = (float*)smem_raw;

    int K, boundk, lda0;
    const __nv_bfloat16 *A0, *A1, *Wm;
    float* cst;
    __nv_bfloat16* hout;
    const int pout = pin ^ 1;

    if (layer == 0) {
        K = K1; boundk = DD; lda0 = DD;
        A0 = g_X + (size_t)t * BB * DD;
        A1 = g_h1[pin];
        Wm = g_W1; cst = g_c1; hout = g_h1[pout];
    } else {
        K = K2; boundk = HH; lda0 = HH;
        A0 = g_h1[pout];
        A1 = g_h2[pin];
        Wm = g_W2; cst = g_c2; hout = g_h2[pout];
    }

    const int n0 = blockIdx.x * 32;
    const int m0 = blockIdx.y * 64;
    const int tid = threadIdx.x;
    const int lane = tid & 31;
    const int wid = tid >> 5;
    const int wm = wid & 3;
    const int wn = wid >> 2;
    const int rowA = tid >> 2;
    const int quadA = tid & 3;

    float acc[8][4];
#pragma unroll
    for (int j = 0; j < 8; j++)
#pragma unroll
        for (int q = 0; q < 4; q++) acc[j][q] = 0.f;

    auto load_stage = [&](int kt, int s) {
        const int k0 = kt * 32;
        const __nv_bfloat16* gpA;
        if (k0 < boundk) gpA = A0 + (size_t)(m0 + rowA) * lda0 + k0 + quadA * 8;
        else             gpA = A1 + (size_t)(m0 + rowA) * HH + (k0 - boundk) + quadA * 8;
        uint32_t dstA = smem_u32(As + s * 64 * AS_STRIDE + rowA * AS_STRIDE + quadA * 8);
        asm volatile("cp.async.cg.shared.global [%0], [%1], 16;\n" :: "r"(dstA), "l"(gpA));
#pragma unroll
        for (int i = 0; i < 2; i++) {
            int c = tid + i * 256;
            int kk = c >> 4;
            int ncv = (c & 15) * 8;
            int g = ncv >> 5;
            int col = g * HH + n0 + (ncv & 31);
            const __nv_bfloat16* gpB = Wm + (size_t)(k0 + kk) * FOURH + col;
            uint32_t dstB = smem_u32(Bs + s * 32 * BS_STRIDE + kk * BS_STRIDE + ncv);
            asm volatile("cp.async.cg.shared.global [%0], [%1], 16;\n" :: "r"(dstB), "l"(gpB));
        }
    };

    load_stage(0, 0);
    asm volatile("cp.async.commit_group;\n" ::: "memory");

    const int nK = K >> 5;
    for (int kt = 0; kt < nK; ++kt) {
        const int s = kt & 1;
        if (kt + 1 < nK) load_stage(kt + 1, s ^ 1);
        asm volatile("cp.async.commit_group;\n" ::: "memory");
        asm volatile("cp.async.wait_group 1;\n" ::: "memory");
        __syncthreads();

#pragma unroll
        for (int ks = 0; ks < 2; ++ks) {
            uint32_t a0, a1, a2, a3;
            {
                int row = wm * 16 + (lane & 15);
                int colb = ks * 16 + (lane >> 4) * 8;
                uint32_t addr = smem_u32(As + s * 64 * AS_STRIDE + row * AS_STRIDE + colb);
                asm volatile("ldmatrix.sync.aligned.m8n8.x4.shared.b16 {%0,%1,%2,%3}, [%4];\n"
                             : "=r"(a0), "=r"(a1), "=r"(a2), "=r"(a3) : "r"(addr));
            }
#pragma unroll
            for (int j2 = 0; j2 < 4; j2++) {
                uint32_t b0, b1, b2, b3;
                int krow = ks * 16 + (lane & 7) + ((lane >> 3) & 1) * 8;
                int ncol = wn * 64 + j2 * 16 + (lane >> 4) * 8;
                uint32_t addr = smem_u32(Bs + s * 32 * BS_STRIDE + krow * BS_STRIDE + ncol);
                asm volatile("ldmatrix.sync.aligned.m8n8.x4.trans.shared.b16 {%0,%1,%2,%3}, [%4];\n"
                             : "=r"(b0), "=r"(b1), "=r"(b2), "=r"(b3) : "r"(addr));
                asm volatile("mma.sync.aligned.m16n8k16.row.col.f32.bf16.bf16.f32 "
                             "{%0,%1,%2,%3}, {%4,%5,%6,%7}, {%8,%9}, {%0,%1,%2,%3};\n"
                             : "+f"(acc[2 * j2][0]), "+f"(acc[2 * j2][1]),
                               "+f"(acc[2 * j2][2]), "+f"(acc[2 * j2][3])
                             : "r"(a0), "r"(a1), "r"(a2), "r"(a3), "r"(b0), "r"(b1));
                asm volatile("mma.sync.aligned.m16n8k16.row.col.f32.bf16.bf16.f32 "
                             "{%0,%1,%2,%3}, {%4,%5,%6,%7}, {%8,%9}, {%0,%1,%2,%3};\n"
                             : "+f"(acc[2 * j2 + 1][0]), "+f"(acc[2 * j2 + 1][1]),
                               "+f"(acc[2 * j2 + 1][2]), "+f"(acc[2 * j2 + 1][3])
                             : "r"(a0), "r"(a1), "r"(a2), "r"(a3), "r"(b2), "r"(b3));
            }
        }
        __syncthreads();
    }

#pragma unroll
    for (int j = 0; j < 8; j++) {
        int col = wn * 64 + j * 8 + (lane & 3) * 2;
        int rr = wm * 16 + (lane >> 2);
        zs[rr * ZS_STRIDE + col]           = acc[j][0];
        zs[rr * ZS_STRIDE + col + 1]       = acc[j][1];
        zs[(rr + 8) * ZS_STRIDE + col]     = acc[j][2];
        zs[(rr + 8) * ZS_STRIDE + col + 1] = acc[j][3];
    }
    __syncthreads();

#pragma unroll
    for (int e = tid; e < 64 * 32; e += 256) {
        int rr = e >> 5;
        int hc = e & 31;
        float zi = zs[rr * ZS_STRIDE + hc]        + bias[0 * HH + n0 + hc];
        float zj = zs[rr * ZS_STRIDE + 32 + hc]   + bias[1 * HH + n0 + hc];
        float zf = zs[rr * ZS_STRIDE + 64 + hc]   + bias[2 * HH + n0 + hc];
        float zo = zs[rr * ZS_STRIDE + 96 + hc]   + bias[3 * HH + n0 + hc];
        int gi = (m0 + rr) * HH + n0 + hc;
        float c = cst[gi];
        float ncell = c * sigmoidf_(zf + 1.f) + sigmoidf_(zi) * tanhf(zj);
        float nh = tanhf(ncell) * sigmoidf_(zo);
        cst[gi] = ncell;
        hout[gi] = __float2bfloat16(nh);
    }
}

// ---------------- dense head + loss ----------------
__global__ void head_kernel(const float* __restrict__ Wd, const float* __restrict__ bd,
                            const float* __restrict__ labels) {
    const int b = blockIdx.x;
    const int lane = threadIdx.x & 31;
    const int w = threadIdx.x >> 5;
    const __nv_bfloat16* h = g_h2[0];  // T=336 even -> final h2 in slot 0
    __shared__ float warpsum[8];
    float total = 0.f;
    for (int l = w; l < 24; l += 8) {
        float s = 0.f;
        for (int k = lane; k < HH; k += 32)
            s += __bfloat162float(h[b * HH + k]) * Wd[k * 24 + l];
#pragma unroll
        for (int off = 16; off; off >>= 1) s += __shfl_xor_sync(0xffffffffu, s, off);
        if (lane == 0) {
            float pred = s + bd[l];
            float e = pred - labels[b * 24 + l];
            total += e * e;
        }
    }
    if (lane == 0) warpsum[w] = total;
    __syncthreads();
    if (threadIdx.x == 0) {
        float acc = 0.f;
#pragma unroll
        for (int i = 0; i < 8; i++) acc += warpsum[i];
        g_partial[b] = acc;
    }
}

__global__ void finish_kernel(float* __restrict__ out) {
    __shared__ float sh[256];
    sh[threadIdx.x] = g_partial[threadIdx.x];
    __syncthreads();
    for (int s = 128; s; s >>= 1) {
        if (threadIdx.x < s) sh[threadIdx.x] += sh[threadIdx.x + s];
        __syncthreads();
    }
    if (threadIdx.x == 0) out[0] = sh[0] / (float)(BB * 24);
}

// ---------------- host: tensormap encoding ----------------
typedef CUresult (*encode_fn_t)(
    CUtensorMap*, CUtensorMapDataType, cuuint32_t, void*,
    const cuuint64_t*, const cuuint64_t*, const cuuint32_t*, const cuuint32_t*,
    CUtensorMapInterleave, CUtensorMapSwizzle, CUtensorMapL2promotion,
    CUtensorMapFloatOOBfill);

static bool encode_map(encode_fn_t enc, CUtensorMap* tm, void* base,
                       uint64_t d0, uint64_t d1, uint64_t d2,
                       uint64_t s1_bytes, uint64_t s2_bytes, uint32_t box_rows) {
    cuuint64_t dims[3] = {d0, d1, d2};
    cuuint64_t strides[2] = {s1_bytes, s2_bytes};
    cuuint32_t box[3] = {64, box_rows, 1};
    cuuint32_t es[3] = {1, 1, 1};
    CUresult res = enc(tm, CU_TENSOR_MAP_DATA_TYPE_BFLOAT16, 3, base,
                       dims, strides, box, es,
                       CU_TENSOR_MAP_INTERLEAVE_NONE, CU_TENSOR_MAP_SWIZZLE_128B,
                       CU_TENSOR_MAP_L2_PROMOTION_L2_128B,
                       CU_TENSOR_MAP_FLOAT_OOB_FILL_NONE);
    return res == CUDA_SUCCESS;
}

// ---------------- launch ----------------
extern "C" void kernel_launch(void* const* d_in, const int* in_sizes, int n_in,
                              void* d_out, int out_size) {
    const float* features = (const float*)d_in[0];
    const float* labels   = (const float*)d_in[1];
    const float* W1       = (const float*)d_in[2];
    const float* b1       = (const float*)d_in[3];
    const float* W2       = (const float*)d_in[4];
    const float* b2       = (const float*)d_in[5];
    const float* Wd       = (const float*)d_in[6];
    const float* bd       = (const float*)d_in[7];
    float* out = (float*)d_out;

    constexpr int SMEM_128 = 6 * 24576 + 1024 + 128 * 133 * 4;  // 216576
    constexpr int SMEM_64  = 6 * 20480 + 1024 + 128 * 69 * 4;   // 159232

    static CUtensorMap tmx, tmh1, tmh2, tmw1, tmw2;
    static int mode = -1;   // 0=mma.sync, 1=<128>/64CTA champion, 2=<64>/128CTA
    if (mode < 0) {
        mode = 0;
        cudaFuncAttributes attr{};
        cudaFuncGetAttributes(&attr, lstm_persist_cg2<128>);
        if (attr.numRegs > 40) {
            void* fp = nullptr;
            cudaDriverEntryPointQueryResult qr = cudaDriverEntryPointSuccess;
            cudaGetDriverEntryPointByVersion("cuTensorMapEncodeTiled", &fp, 12000,
                                             cudaEnableDefault, &qr);
            void *px = nullptr, *ph1 = nullptr, *ph2 = nullptr, *pw1 = nullptr, *pw2 = nullptr;
            cudaGetSymbolAddress(&px, g_X);
            cudaGetSymbolAddress(&ph1, g_h1);
            cudaGetSymbolAddress(&ph2, g_h2);
            cudaGetSymbolAddress(&pw1, g_W1);
            cudaGetSymbolAddress(&pw2, g_W2);
            if (fp && px && ph1 && ph2 && pw1 && pw2) {
                // can <64> run 32 co-resident clusters (128 CTAs)?
                int use64 = 0;
                if (cudaFuncSetAttribute(lstm_persist_cg2<64>,
                        cudaFuncAttributeMaxDynamicSharedMemorySize, SMEM_64)
                        == cudaSuccess) {
                    cudaLaunchConfig_t qcfg = {};
                    qcfg.gridDim = dim3(128, 1, 1);
                    qcfg.blockDim = dim3(256, 1, 1);
                    qcfg.dynamicSmemBytes = SMEM_64;
                    cudaLaunchAttribute qat[1];
                    qat[0].id = cudaLaunchAttributeClusterDimension;
                    qat[0].val.clusterDim = {4, 1, 1};
                    qcfg.attrs = qat;
                    qcfg.numAttrs = 1;
                    int nclust = 0;
                    if (cudaOccupancyMaxActiveClusters(&nclust, lstm_persist_cg2<64>, &qcfg)
                            == cudaSuccess && nclust >= 32)
                        use64 = 1;
                }
                const uint32_t wrows = use64 ? 32u : 64u;
                encode_fn_t enc = (encode_fn_t)fp;
                bool ok = true;
                ok &= encode_map(enc, &tmx,  px,  DD, BB, TT, (uint64_t)DD * 2, (uint64_t)BB * DD * 2, 64);
                ok &= encode_map(enc, &tmh1, ph1, HH, BB, 2,  (uint64_t)HH * 2, (uint64_t)BB * HH * 2, 64);
                ok &= encode_map(enc, &tmh2, ph2, HH, BB, 2,  (uint64_t)HH * 2, (uint64_t)BB * HH * 2, 64);
                ok &= encode_map(enc, &tmw1, pw1, K1, FOURH, 1, (uint64_t)K1 * 2, (uint64_t)K1 * FOURH * 2, wrows);
                ok &= encode_map(enc, &tmw2, pw2, K2, FOURH, 1, (uint64_t)K2 * 2, (uint64_t)K2 * FOURH * 2, wrows);
                if (ok) {
                    if (use64) {
                        mode = 2;
                    } else if (cudaFuncSetAttribute(lstm_persist_cg2<128>,
                               cudaFuncAttributeMaxDynamicSharedMemorySize, SMEM_128)
                               == cudaSuccess) {
                        mode = 1;
                    }
                }
            }
        }
    }

    if (mode == 2)      conv_w_t<<<dim3(K1 / 32, 32, 4), dim3(32, 8)>>>(W1, 0, K1, 16);
    else if (mode == 1) conv_w_t<<<dim3(K1 / 32, 32, 4), dim3(32, 8)>>>(W1, 0, K1, 32);
    else                conv_w_kernel<<<592, 256>>>(W1, 0, K1 * FOURH);
    if (mode == 2)      conv_w_t<<<dim3(K2 / 32, 32, 4), dim3(32, 8)>>>(W2, 1, K2, 16);
    else if (mode == 1) conv_w_t<<<dim3(K2 / 32, 32, 4), dim3(32, 8)>>>(W2, 1, K2, 32);
    else                conv_w_kernel<<<592, 256>>>(W2, 1, K2 * FOURH);
    conv_x_kernel<<<592, 256>>>(features);
    init_state_kernel<<<512, 256>>>();

    if (mode == 2) {
        cudaLaunchConfig_t cfg = {};
        cfg.gridDim = dim3(128, 1, 1);
        cfg.blockDim = dim3(256, 1, 1);
        cfg.dynamicSmemBytes = SMEM_64;
        cudaLaunchAttribute at[1];
        at[0].id = cudaLaunchAttributeClusterDimension;
        at[0].val.clusterDim = {4, 1, 1};
        cfg.attrs = at;
        cfg.numAttrs = 1;
        cudaLaunchKernelEx(&cfg, lstm_persist_cg2<64>, tmx, tmh1, tmh2, tmw1, tmw2, b1, b2);
    } else if (mode == 1) {
        cudaLaunchConfig_t cfg = {};
        cfg.gridDim = dim3(64, 1, 1);
        cfg.blockDim = dim3(256, 1, 1);
        cfg.dynamicSmemBytes = SMEM_128;
        cudaLaunchAttribute at[1];
        at[0].id = cudaLaunchAttributeClusterDimension;
        at[0].val.clusterDim = {4, 1, 1};
        cfg.attrs = at;
        cfg.numAttrs = 1;
        cudaLaunchKernelEx(&cfg, lstm_persist_cg2<128>, tmx, tmh1, tmh2, tmw1, tmw2, b1, b2);
    } else {
        dim3 grid(32, 4);
        for (int t = 0; t < TT; t++) {
            int p = t & 1;
            lstm_step_fb<<<grid, 256>>>(0, t, p, b1);
            lstm_step_fb<<<grid, 256>>>(1, t, p, b2);
        }
    }

    head_kernel<<<BB, 256>>>(Wd, bd, labels);
    finish_kernel<<<1, 256>>>(out);
}